// round 1
// baseline (speedup 1.0000x reference)
#include <cuda_runtime.h>
#include <math.h>

// Problem constants
#define BATCH 64
#define EMBED 512
#define HID   1024
#define G4    4096          // 4*HID
#define VOCAB 50257
#define TSTEPS 18
#define MROWS (BATCH*TSTEPS)  // 1152

// ---------------- device scratch (allocation-free: static device globals) ----
__device__ float g_gate_base[BATCH * G4];   // x_proj + b_ih + b_hh   (1 MB)
__device__ float g_hA[BATCH * HID];
__device__ float g_hB[BATCH * HID];
__device__ float g_c [BATCH * HID];
__device__ float g_Hbuf[MROWS * HID];       // h_t laid out as m = b*T + t (4.7 MB)

// ---------------------------------------------------------------- init ------
__global__ void init_kernel() {
    int i = blockIdx.x * blockDim.x + threadIdx.x;
    if (i < BATCH * HID) { g_hA[i] = 0.f; g_c[i] = 0.f; }
}

// ------------------------------------------------ x_proj = feat@W_ih^T + b --
// grid = 128 blocks (32 gate-rows each), 256 threads.
// features tile [64 x 128] staged in smem per K-chunk; each thread owns
// 1 gate-row x 8 batches.
__global__ void xproj_kernel(const float4* __restrict__ feat4,
                             const float4* __restrict__ wih4,
                             const float*  __restrict__ b_ih,
                             const float*  __restrict__ b_hh) {
    __shared__ float4 fs[BATCH * 32];      // [b][eq] chunk of 128 floats, 32KB
    int tid = threadIdx.x;
    int rl  = tid & 31;          // row within block's 32-row slab
    int bg  = tid >> 5;          // batch group (0..7), 8 batches each
    int r   = blockIdx.x * 32 + rl;

    float acc[8];
#pragma unroll
    for (int j = 0; j < 8; j++) acc[j] = 0.f;

    for (int ec = 0; ec < 4; ec++) {       // 4 chunks of 128 over EMBED=512
        __syncthreads();
#pragma unroll
        for (int i = 0; i < 8; i++) {
            int lin = i * 256 + tid;           // 0..2047
            int b = lin >> 5, q = lin & 31;
            fs[lin] = feat4[b * 128 + ec * 32 + q];
        }
        __syncthreads();
#pragma unroll 4
        for (int eq = 0; eq < 32; eq++) {
            float4 w = wih4[r * 128 + ec * 32 + eq];
#pragma unroll
            for (int jj = 0; jj < 8; jj++) {
                float4 f = fs[(bg * 8 + jj) * 32 + eq];
                acc[jj] += w.x * f.x + w.y * f.y + w.z * f.z + w.w * f.w;
            }
        }
    }
    float bias = b_ih[r] + b_hh[r];
#pragma unroll
    for (int jj = 0; jj < 8; jj++)
        g_gate_base[(bg * 8 + jj) * G4 + r] = acc[jj] + bias;
}

// ------------------------------------------------ one fused LSTM step -------
// grid = 256 blocks (4 hidden units each -> 16 W_hh rows), 256 threads.
// Full-K per block so the gate nonlinearity fuses into the same launch.
// Ping-pong h buffers (read t%2==0 ? A : B) to avoid cross-block RAW races.
__global__ void lstm_step_kernel(const float4* __restrict__ whh4, int t) {
    const float4* hin4 = (const float4*)((t & 1) ? g_hB : g_hA);
    float*        hout =                 (t & 1) ? g_hA : g_hB;

    __shared__ float4 hs[BATCH * 32];      // [b][kq] chunk of 128 K, 32KB
    float* gs = (float*)hs;                // reused for gate exchange (4KB)

    int tid = threadIdx.x;
    int rl  = tid & 15;                    // which of 16 gate rows
    int bg  = tid >> 4;                    // batch group (0..15), 4 batches each
    int j0  = blockIdx.x * 4;              // hidden-unit base
    int gi  = rl >> 2, jl = rl & 3;
    int r   = gi * HID + j0 + jl;          // W_hh row (gate-major layout)

    float acc[4] = {0.f, 0.f, 0.f, 0.f};

    for (int kc = 0; kc < 8; kc++) {       // 8 chunks of 128 over K=1024
        __syncthreads();
#pragma unroll
        for (int i = 0; i < 8; i++) {
            int lin = i * 256 + tid;
            int b = lin >> 5, q = lin & 31;
            hs[lin] = hin4[b * 256 + kc * 32 + q];
        }
        __syncthreads();
#pragma unroll 4
        for (int eq = 0; eq < 32; eq++) {
            float4 w = whh4[r * 256 + kc * 32 + eq];
#pragma unroll
            for (int jj = 0; jj < 4; jj++) {
                float4 f = hs[(bg * 4 + jj) * 32 + eq];
                acc[jj] += w.x * f.x + w.y * f.y + w.z * f.z + w.w * f.w;
            }
        }
    }
    __syncthreads();
#pragma unroll
    for (int jj = 0; jj < 4; jj++) {
        int b = bg * 4 + jj;
        gs[rl * 64 + b] = acc[jj] + g_gate_base[b * G4 + r];
    }
    __syncthreads();
    {   // 256 threads == 64 batches x 4 hidden units: full gate fusion
        int b  = tid >> 2;
        int j2 = tid & 3;
        float xi = gs[(0 * 4 + j2) * 64 + b];
        float xf = gs[(1 * 4 + j2) * 64 + b];
        float xg = gs[(2 * 4 + j2) * 64 + b];
        float xo = gs[(3 * 4 + j2) * 64 + b];
        float iv = 1.f / (1.f + expf(-xi));
        float fv = 1.f / (1.f + expf(-xf));
        float gv = tanhf(xg);
        float ov = 1.f / (1.f + expf(-xo));
        int j  = j0 + j2;
        int ci = b * HID + j;
        float c = fv * g_c[ci] + iv * gv;
        g_c[ci] = c;
        float h = ov * tanhf(c);
        hout[ci] = h;
        g_Hbuf[(b * TSTEPS + t) * HID + j] = h;
    }
}

// --------------------------- vocab projection: [1152,1024]x[1024,50257] -----
// Classic SGEMM: 128x128 block tile, BK=16, 256 threads, 8x8 per thread.
__global__ void __launch_bounds__(256, 2)
out_gemm_kernel(const float4* __restrict__ wfc4,
                const float*  __restrict__ b_fc,
                float* __restrict__ out) {
    __shared__ float As[16][128];
    __shared__ float Bs[16][128];

    int tid = threadIdx.x;
    int tx  = tid & 15;          // n-direction (8 cols each)
    int ty  = tid >> 4;          // m-direction (8 rows each)
    int n0  = blockIdx.x * 128;
    int m0  = blockIdx.y * 128;

    const float4* A4 = (const float4*)g_Hbuf;   // [MROWS, HID] row-major

    float acc[8][8];
#pragma unroll
    for (int i = 0; i < 8; i++)
#pragma unroll
        for (int j = 0; j < 8; j++) acc[i][j] = 0.f;

    for (int k0 = 0; k0 < HID; k0 += 16) {
        // stage A tile (128 rows x 16 k), transposed into As[k][m]
#pragma unroll
        for (int i = 0; i < 2; i++) {
            int f  = tid * 2 + i;             // 0..511
            int mm = f >> 2, kq = f & 3;
            float4 v = A4[(m0 + mm) * 256 + (k0 >> 2) + kq];
            As[kq * 4 + 0][mm] = v.x;
            As[kq * 4 + 1][mm] = v.y;
            As[kq * 4 + 2][mm] = v.z;
            As[kq * 4 + 3][mm] = v.w;
        }
        // stage B tile: Bs[k][n] = W_fc[n0+n][k0+k]  (guarded: V not /128)
#pragma unroll
        for (int i = 0; i < 2; i++) {
            int f  = tid * 2 + i;
            int nn = f >> 2, kq = f & 3;
            int row = n0 + nn;
            float4 v = make_float4(0.f, 0.f, 0.f, 0.f);
            if (row < VOCAB) v = wfc4[row * 256 + (k0 >> 2) + kq];
            Bs[kq * 4 + 0][nn] = v.x;
            Bs[kq * 4 + 1][nn] = v.y;
            Bs[kq * 4 + 2][nn] = v.z;
            Bs[kq * 4 + 3][nn] = v.w;
        }
        __syncthreads();
#pragma unroll
        for (int kk = 0; kk < 16; kk++) {
            float a[8], b[8];
            *(float4*)&a[0] = *(const float4*)&As[kk][ty * 8];
            *(float4*)&a[4] = *(const float4*)&As[kk][ty * 8 + 4];
            *(float4*)&b[0] = *(const float4*)&Bs[kk][tx * 8];
            *(float4*)&b[4] = *(const float4*)&Bs[kk][tx * 8 + 4];
#pragma unroll
            for (int i = 0; i < 8; i++)
#pragma unroll
                for (int j = 0; j < 8; j++)
                    acc[i][j] += a[i] * b[j];
        }
        __syncthreads();
    }

    // epilogue: out[m, n] = acc + b_fc[n];  m = b*T+t matches [b,t,v] layout
#pragma unroll
    for (int i = 0; i < 8; i++) {
        int m = m0 + ty * 8 + i;             // always < 1152
        size_t rowbase = (size_t)m * VOCAB;
#pragma unroll
        for (int j = 0; j < 8; j++) {
            int n = n0 + tx * 8 + j;
            if (n < VOCAB) out[rowbase + n] = acc[i][j] + b_fc[n];
        }
    }
}

// ---------------------------------------------------------------------------
extern "C" void kernel_launch(void* const* d_in, const int* in_sizes, int n_in,
                              void* d_out, int out_size) {
    const float* features = (const float*)d_in[0];
    const float* W_ih     = (const float*)d_in[1];
    const float* W_hh     = (const float*)d_in[2];
    const float* b_ih     = (const float*)d_in[3];
    const float* b_hh     = (const float*)d_in[4];
    const float* W_fc     = (const float*)d_in[5];
    const float* b_fc     = (const float*)d_in[6];
    (void)in_sizes; (void)n_in; (void)out_size;   // max_seq_len fixed = 18

    init_kernel<<<(BATCH * HID + 255) / 256, 256>>>();
    xproj_kernel<<<128, 256>>>((const float4*)features, (const float4*)W_ih,
                               b_ih, b_hh);
    for (int t = 0; t < TSTEPS; t++)
        lstm_step_kernel<<<256, 256>>>((const float4*)W_hh, t);

    dim3 grid((VOCAB + 127) / 128, MROWS / 128);
    out_gemm_kernel<<<grid, 256>>>((const float4*)W_fc, b_fc, (float*)d_out);
}

// round 3
// speedup vs baseline: 2.2825x; 2.2825x over previous
#include <cuda_runtime.h>
#include <cuda_bf16.h>
#include <math.h>
#include <stdint.h>

#define BATCH  64
#define EMBED  512
#define HID    1024
#define G4     4096
#define VOCAB  50257
#define TSTEPS 18
#define MROWS  (BATCH*TSTEPS)   // 1152
#define KDIM   1024
#define KTOT   3072             // 3 bf16 passes concatenated

// ---------------- device scratch (static device globals; no allocs) ---------
__device__ float g_gate_base[BATCH * G4];
__device__ float g_hA[BATCH * HID];
__device__ float g_hB[BATCH * HID];
__device__ float g_c [BATCH * HID];
__device__ float g_Hbuf[MROWS * HID];
__device__ __nv_bfloat16 g_Acat[MROWS * KTOT];           // [Ahi|Ahi|Alo]  7 MB
__device__ __nv_bfloat16 g_Bcat[(size_t)VOCAB * KTOT];   // [Bhi|Blo|Bhi] 309 MB

// ---------------------------------------------------------------- helpers ---
__device__ __forceinline__ uint32_t smem_u32(const void* p) {
    uint32_t a;
    asm("{ .reg .u64 t; cvta.to.shared.u64 t, %1; cvt.u32.u64 %0, t; }"
        : "=r"(a) : "l"(p));
    return a;
}
__device__ __forceinline__ void cp16(uint32_t s, const void* g) {
    asm volatile("cp.async.cg.shared.global [%0], [%1], 16;" :: "r"(s), "l"(g) : "memory");
}
__device__ __forceinline__ void cp_commit() {
    asm volatile("cp.async.commit_group;" ::: "memory");
}
__device__ __forceinline__ void cp_wait1() {
    asm volatile("cp.async.wait_group 1;" ::: "memory");
}
__device__ __forceinline__ void ldsm4(uint32_t* r, uint32_t a) {
    asm volatile("ldmatrix.sync.aligned.m8n8.x4.shared.b16 {%0,%1,%2,%3}, [%4];"
                 : "=r"(r[0]), "=r"(r[1]), "=r"(r[2]), "=r"(r[3]) : "r"(a));
}
__device__ __forceinline__ void mma16816(float* c, const uint32_t* a, const uint32_t* b) {
    asm volatile(
        "mma.sync.aligned.m16n8k16.row.col.f32.bf16.bf16.f32 "
        "{%0,%1,%2,%3},{%4,%5,%6,%7},{%8,%9},{%0,%1,%2,%3};"
        : "+f"(c[0]), "+f"(c[1]), "+f"(c[2]), "+f"(c[3])
        : "r"(a[0]), "r"(a[1]), "r"(a[2]), "r"(a[3]), "r"(b[0]), "r"(b[1]));
}

// ---------------------------------------------------------------- init ------
__global__ void init_kernel() {
    int i = blockIdx.x * blockDim.x + threadIdx.x;
    if (i < BATCH * HID) { g_hA[i] = 0.f; g_c[i] = 0.f; }
}

// ------------------------------------------------ x_proj = feat@W_ih^T + b --
__global__ void xproj_kernel(const float4* __restrict__ feat4,
                             const float4* __restrict__ wih4,
                             const float*  __restrict__ b_ih,
                             const float*  __restrict__ b_hh) {
    __shared__ float4 fs[BATCH * 32];
    int tid = threadIdx.x;
    int rl  = tid & 31;
    int bg  = tid >> 5;
    int r   = blockIdx.x * 32 + rl;
    float acc[8];
#pragma unroll
    for (int j = 0; j < 8; j++) acc[j] = 0.f;
    for (int ec = 0; ec < 4; ec++) {
        __syncthreads();
#pragma unroll
        for (int i = 0; i < 8; i++) {
            int lin = i * 256 + tid;
            int b = lin >> 5, q = lin & 31;
            fs[lin] = feat4[b * 128 + ec * 32 + q];
        }
        __syncthreads();
#pragma unroll 4
        for (int eq = 0; eq < 32; eq++) {
            float4 w = wih4[r * 128 + ec * 32 + eq];
#pragma unroll
            for (int jj = 0; jj < 8; jj++) {
                float4 f = fs[(bg * 8 + jj) * 32 + eq];
                acc[jj] += w.x * f.x + w.y * f.y + w.z * f.z + w.w * f.w;
            }
        }
    }
    float bias = b_ih[r] + b_hh[r];
#pragma unroll
    for (int jj = 0; jj < 8; jj++)
        g_gate_base[(bg * 8 + jj) * G4 + r] = acc[jj] + bias;
}

// ------------------------------------------------ fused LSTM step v2 --------
__global__ void __launch_bounds__(128)
lstm_step2(const float4* __restrict__ whh4, int t) {
    const float4* hin4 = (const float4*)((t & 1) ? g_hB : g_hA);
    float*        hout =                 (t & 1) ? g_hA : g_hB;

    __shared__ float pool[2048 + 32];
    float* As = pool;          // [16][32]
    float* Bs = pool + 512;    // [16][64]

    int tid = threadIdx.x;
    int j0  = blockIdx.x * 8;
    int tx  = tid & 15;
    int ty  = tid >> 4;

    int lrl = tid >> 2;
    int lkq = tid & 3;
    int lg  = lrl >> 3, ljl = lrl & 7;
    int lr  = lg * HID + j0 + ljl;

    float acc[4][4];
#pragma unroll
    for (int i = 0; i < 4; i++)
#pragma unroll
        for (int j = 0; j < 4; j++) acc[i][j] = 0.f;

    for (int k0 = 0; k0 < KDIM; k0 += 16) {
        __syncthreads();
        {
            float4 v = whh4[lr * 256 + (k0 >> 2) + lkq];
            As[(lkq * 4 + 0) * 32 + lrl] = v.x;
            As[(lkq * 4 + 1) * 32 + lrl] = v.y;
            As[(lkq * 4 + 2) * 32 + lrl] = v.z;
            As[(lkq * 4 + 3) * 32 + lrl] = v.w;
        }
#pragma unroll
        for (int i = 0; i < 2; i++) {
            int f  = i * 128 + tid;
            int bb = f >> 2, kq = f & 3;
            float4 v = hin4[bb * 256 + (k0 >> 2) + kq];
            Bs[(kq * 4 + 0) * 64 + bb] = v.x;
            Bs[(kq * 4 + 1) * 64 + bb] = v.y;
            Bs[(kq * 4 + 2) * 64 + bb] = v.z;
            Bs[(kq * 4 + 3) * 64 + bb] = v.w;
        }
        __syncthreads();
#pragma unroll
        for (int kk = 0; kk < 16; kk++) {
            float4 a4 = *(const float4*)&As[kk * 32 + ty * 4];
            float4 b4 = *(const float4*)&Bs[kk * 64 + tx * 4];
            float a[4] = {a4.x, a4.y, a4.z, a4.w};
            float b[4] = {b4.x, b4.y, b4.z, b4.w};
#pragma unroll
            for (int i = 0; i < 4; i++)
#pragma unroll
                for (int j = 0; j < 4; j++) acc[i][j] += a[i] * b[j];
        }
    }
    __syncthreads();
    float* gs = pool;
#pragma unroll
    for (int i = 0; i < 4; i++) {
        int rl = ty * 4 + i;
        int g  = rl >> 3, jl = rl & 7;
        int r  = g * HID + j0 + jl;
#pragma unroll
        for (int j = 0; j < 4; j++) {
            int b = tx * 4 + j;
            gs[rl * 64 + b] = acc[i][j] + g_gate_base[b * G4 + r];
        }
    }
    __syncthreads();
    {
        int fjl = tid >> 4;
#pragma unroll
        for (int jj = 0; jj < 4; jj++) {
            int b  = (tid & 15) * 4 + jj;
            float xi = gs[(0 * 8 + fjl) * 64 + b];
            float xf = gs[(1 * 8 + fjl) * 64 + b];
            float xg = gs[(2 * 8 + fjl) * 64 + b];
            float xo = gs[(3 * 8 + fjl) * 64 + b];
            float iv = 1.f / (1.f + expf(-xi));
            float fv = 1.f / (1.f + expf(-xf));
            float gv = tanhf(xg);
            float ov = 1.f / (1.f + expf(-xo));
            int j  = j0 + fjl;
            int ci = b * HID + j;
            float c = fv * g_c[ci] + iv * gv;
            g_c[ci] = c;
            float h = ov * tanhf(c);
            hout[ci] = h;
            g_Hbuf[(b * TSTEPS + t) * HID + j] = h;
        }
    }
}

// ---------------------------------------- fp32 -> bf16 hi/lo concat ---------
// B' row layout per vocab row n: [Bhi(0:1024) | Blo(1024:2048) | Bhi(2048:3072)]
__global__ void convW_kernel(const float4* __restrict__ w) {
    int n = blockIdx.x;              // vocab row
    int q = threadIdx.x;             // quad 0..255
    float4 v = w[(size_t)n * 256 + q];
    float x[4] = {v.x, v.y, v.z, v.w};
    __nv_bfloat16 hi[4], lo[4];
#pragma unroll
    for (int j = 0; j < 4; j++) {
        hi[j] = __float2bfloat16_rn(x[j]);
        lo[j] = __float2bfloat16_rn(x[j] - __bfloat162float(hi[j]));
    }
    uint32_t h01 = ((uint32_t)__bfloat16_as_ushort(hi[1]) << 16) | __bfloat16_as_ushort(hi[0]);
    uint32_t h23 = ((uint32_t)__bfloat16_as_ushort(hi[3]) << 16) | __bfloat16_as_ushort(hi[2]);
    uint32_t l01 = ((uint32_t)__bfloat16_as_ushort(lo[1]) << 16) | __bfloat16_as_ushort(lo[0]);
    uint32_t l23 = ((uint32_t)__bfloat16_as_ushort(lo[3]) << 16) | __bfloat16_as_ushort(lo[2]);
    uint2* base = (uint2*)(g_Bcat + (size_t)n * KTOT);
    base[q]        = make_uint2(h01, h23);   // chunk 0: hi
    base[256 + q]  = make_uint2(l01, l23);   // chunk 1: lo
    base[512 + q]  = make_uint2(h01, h23);   // chunk 2: hi
}
// A' row layout per m row: [Ahi | Ahi | Alo]
__global__ void convH_kernel() {
    int m = blockIdx.x;
    int q = threadIdx.x;
    float4 v = ((const float4*)g_Hbuf)[(size_t)m * 256 + q];
    float x[4] = {v.x, v.y, v.z, v.w};
    __nv_bfloat16 hi[4], lo[4];
#pragma unroll
    for (int j = 0; j < 4; j++) {
        hi[j] = __float2bfloat16_rn(x[j]);
        lo[j] = __float2bfloat16_rn(x[j] - __bfloat162float(hi[j]));
    }
    uint32_t h01 = ((uint32_t)__bfloat16_as_ushort(hi[1]) << 16) | __bfloat16_as_ushort(hi[0]);
    uint32_t h23 = ((uint32_t)__bfloat16_as_ushort(hi[3]) << 16) | __bfloat16_as_ushort(hi[2]);
    uint32_t l01 = ((uint32_t)__bfloat16_as_ushort(lo[1]) << 16) | __bfloat16_as_ushort(lo[0]);
    uint32_t l23 = ((uint32_t)__bfloat16_as_ushort(lo[3]) << 16) | __bfloat16_as_ushort(lo[2]);
    uint2* base = (uint2*)(g_Acat + (size_t)m * KTOT);
    base[q]       = make_uint2(h01, h23);
    base[256 + q] = make_uint2(h01, h23);
    base[512 + q] = make_uint2(l01, l23);
}

// --------------------- vocab projection: mma.sync bf16, 128x128x32 ----------
#define BK      32
#define NITER   (KTOT / BK)          // 96
#define APITCH  80                   // (BK+8)*2 bytes: pads ldmatrix banks
#define TILEB   (128 * APITCH)       // 10240
#define STAGEB  (2 * TILEB)          // 20480
#define NSTAGE  3
#define SMEMB   (NSTAGE * STAGEB)    // 61440

__device__ __forceinline__ void gemm_load(uint32_t sbase, int stage, int it,
                                          int tid, int m0, int n0) {
    int kk0 = it * BK;
    uint32_t sA = sbase + (uint32_t)stage * STAGEB;
    uint32_t sB = sA + TILEB;
#pragma unroll
    for (int r = 0; r < 2; r++) {
        int f = r * 256 + tid;
        int row = f >> 2, q = f & 3;
        cp16(sA + (uint32_t)(row * APITCH + q * 16),
             g_Acat + (size_t)(m0 + row) * KTOT + kk0 + q * 8);
    }
#pragma unroll
    for (int r = 0; r < 2; r++) {
        int f = r * 256 + tid;
        int row = f >> 2, q = f & 3;
        int n = n0 + row;
        if (n > VOCAB - 1) n = VOCAB - 1;          // clamp: results discarded
        cp16(sB + (uint32_t)(row * APITCH + q * 16),
             g_Bcat + (size_t)n * KTOT + kk0 + q * 8);
    }
}

__global__ void __launch_bounds__(256, 2)
vocab_gemm_hmma(const float* __restrict__ b_fc, float* __restrict__ out) {
    extern __shared__ char sm[];
    uint32_t sbase = smem_u32(sm);
    int tid = threadIdx.x, lane = tid & 31, wid = tid >> 5;
    int wm = wid & 3, wn = wid >> 2;           // warp tile 32(m) x 64(n)
    int m0 = blockIdx.x * 128;                 // 9 m-tiles (fastest -> L2 B reuse)
    int n0 = blockIdx.y * 128;                 // 393 n-tiles

    float acc[2][8][4];
#pragma unroll
    for (int i = 0; i < 2; i++)
#pragma unroll
        for (int j = 0; j < 8; j++)
#pragma unroll
            for (int k = 0; k < 4; k++) acc[i][j][k] = 0.f;

    gemm_load(sbase, 0, 0, tid, m0, n0); cp_commit();
    gemm_load(sbase, 1, 1, tid, m0, n0); cp_commit();

    for (int it = 0; it < NITER; it++) {
        cp_wait1();
        __syncthreads();
        if (it + 2 < NITER) gemm_load(sbase, (it + 2) % NSTAGE, it + 2, tid, m0, n0);
        cp_commit();

        uint32_t sA = sbase + (uint32_t)(it % NSTAGE) * STAGEB;
        uint32_t sB = sA + TILEB;
#pragma unroll
        for (int kk = 0; kk < 2; kk++) {       // two k16 halves of BK=32
            uint32_t a[2][4], b[4][4];
#pragma unroll
            for (int mt = 0; mt < 2; mt++)
                ldsm4(a[mt], sA + (uint32_t)((wm * 32 + mt * 16 + (lane & 15)) * APITCH
                                             + kk * 32 + (lane >> 4) * 16));
#pragma unroll
            for (int bq = 0; bq < 4; bq++) {
                int nrow = wn * 64 + bq * 16 + ((lane >> 4) << 3) + (lane & 7);
                int kh   = (lane >> 3) & 1;
                ldsm4(b[bq], sB + (uint32_t)(nrow * APITCH + kk * 32 + kh * 16));
            }
#pragma unroll
            for (int mt = 0; mt < 2; mt++)
#pragma unroll
                for (int nt = 0; nt < 8; nt++)
                    mma16816(acc[mt][nt], a[mt], &b[nt >> 1][(nt & 1) * 2]);
        }
        __syncthreads();
    }

    // epilogue: c frag (t/4, (t%4)*2+e) rows +0/+8
#pragma unroll
    for (int mt = 0; mt < 2; mt++) {
        int r0 = m0 + wm * 32 + mt * 16 + (lane >> 2);
        float* o0 = out + (size_t)r0 * VOCAB;
        float* o1 = out + (size_t)(r0 + 8) * VOCAB;
#pragma unroll
        for (int nt = 0; nt < 8; nt++) {
            int col = n0 + wn * 64 + nt * 8 + (lane & 3) * 2;
            if (col < VOCAB) {
                float bz = b_fc[col];
                o0[col] = acc[mt][nt][0] + bz;
                o1[col] = acc[mt][nt][2] + bz;
            }
            if (col + 1 < VOCAB) {
                float bz = b_fc[col + 1];
                o0[col + 1] = acc[mt][nt][1] + bz;
                o1[col + 1] = acc[mt][nt][3] + bz;
            }
        }
    }
}

// ---------------------------------------------------------------------------
extern "C" void kernel_launch(void* const* d_in, const int* in_sizes, int n_in,
                              void* d_out, int out_size) {
    const float* features = (const float*)d_in[0];
    const float* W_ih     = (const float*)d_in[1];
    const float* W_hh     = (const float*)d_in[2];
    const float* b_ih     = (const float*)d_in[3];
    const float* b_hh     = (const float*)d_in[4];
    const float* W_fc     = (const float*)d_in[5];
    const float* b_fc     = (const float*)d_in[6];
    (void)in_sizes; (void)n_in; (void)out_size;

    cudaFuncSetAttribute(vocab_gemm_hmma,
                         cudaFuncAttributeMaxDynamicSharedMemorySize, SMEMB);

    init_kernel<<<(BATCH * HID + 255) / 256, 256>>>();
    xproj_kernel<<<128, 256>>>((const float4*)features, (const float4*)W_ih,
                               b_ih, b_hh);
    convW_kernel<<<VOCAB, 256>>>((const float4*)W_fc);

    for (int t = 0; t < TSTEPS; t++)
        lstm_step2<<<128, 128>>>((const float4*)W_hh, t);

    convH_kernel<<<MROWS, 256>>>();

    dim3 grid(MROWS / 128, (VOCAB + 127) / 128);   // (9, 393)
    vocab_gemm_hmma<<<grid, 256, SMEMB>>>(b_fc, (float*)d_out);
}

// round 4
// speedup vs baseline: 3.0183x; 1.3223x over previous
#include <cuda_runtime.h>
#include <cuda_bf16.h>
#include <math.h>
#include <stdint.h>

#define BATCH  64
#define EMBED  512
#define HID    1024
#define G4     4096
#define VOCAB  50257
#define TSTEPS 18
#define MROWS  (BATCH*TSTEPS)   // 1152
#define KDIM   1024
#define NSPLIT 8                // LSTM k-splits

// ---------------- device scratch (static device globals; no allocs) ---------
__device__ float g_gate_base[G4 * BATCH];          // [r][b]
__device__ float g_hA[HID * BATCH];                // [j][b]
__device__ float g_hB[HID * BATCH];
__device__ float g_c [HID * BATCH];                // [j][b]
__device__ float g_part[NSPLIT * G4 * BATCH];      // [ks][r][b]  8 MB
__device__ __nv_bfloat16 g_Ahi[MROWS * KDIM];      // [m][k]
__device__ __nv_bfloat16 g_Alo[MROWS * KDIM];
__device__ __nv_bfloat16 g_Whi[(size_t)VOCAB * KDIM];   // 103 MB
__device__ __nv_bfloat16 g_Wlo[(size_t)VOCAB * KDIM];   // 103 MB

// ---------------------------------------------------------------- helpers ---
__device__ __forceinline__ uint32_t smem_u32(const void* p) {
    uint32_t a;
    asm("{ .reg .u64 t; cvta.to.shared.u64 t, %1; cvt.u32.u64 %0, t; }"
        : "=r"(a) : "l"(p));
    return a;
}
__device__ __forceinline__ void cp16(uint32_t s, const void* g) {
    asm volatile("cp.async.cg.shared.global [%0], [%1], 16;" :: "r"(s), "l"(g) : "memory");
}
__device__ __forceinline__ void cp_commit() {
    asm volatile("cp.async.commit_group;" ::: "memory");
}
__device__ __forceinline__ void cp_wait1() {
    asm volatile("cp.async.wait_group 1;" ::: "memory");
}
__device__ __forceinline__ void ldsm4(uint32_t* r, uint32_t a) {
    asm volatile("ldmatrix.sync.aligned.m8n8.x4.shared.b16 {%0,%1,%2,%3}, [%4];"
                 : "=r"(r[0]), "=r"(r[1]), "=r"(r[2]), "=r"(r[3]) : "r"(a));
}
__device__ __forceinline__ void mma16816(float* c, const uint32_t* a, const uint32_t* b) {
    asm volatile(
        "mma.sync.aligned.m16n8k16.row.col.f32.bf16.bf16.f32 "
        "{%0,%1,%2,%3},{%4,%5,%6,%7},{%8,%9},{%0,%1,%2,%3};"
        : "+f"(c[0]), "+f"(c[1]), "+f"(c[2]), "+f"(c[3])
        : "r"(a[0]), "r"(a[1]), "r"(a[2]), "r"(a[3]), "r"(b[0]), "r"(b[1]));
}

// ---------------------------------------------------------------- init ------
__global__ void init_kernel() {
    int i = blockIdx.x * blockDim.x + threadIdx.x;
    if (i < HID * BATCH) { g_hA[i] = 0.f; g_c[i] = 0.f; }
}

// ------------------------------------------------ x_proj = feat@W_ih^T + b --
// writes gate_base[r*64 + b]
__global__ void xproj_kernel(const float4* __restrict__ feat4,
                             const float4* __restrict__ wih4,
                             const float*  __restrict__ b_ih,
                             const float*  __restrict__ b_hh) {
    __shared__ float4 fs[BATCH * 32];
    int tid = threadIdx.x;
    int rl  = tid & 31;
    int bg  = tid >> 5;
    int r   = blockIdx.x * 32 + rl;
    float acc[8];
#pragma unroll
    for (int j = 0; j < 8; j++) acc[j] = 0.f;
    for (int ec = 0; ec < 4; ec++) {
        __syncthreads();
#pragma unroll
        for (int i = 0; i < 8; i++) {
            int lin = i * 256 + tid;
            int b = lin >> 5, q = lin & 31;
            fs[lin] = feat4[b * 128 + ec * 32 + q];
        }
        __syncthreads();
#pragma unroll 4
        for (int eq = 0; eq < 32; eq++) {
            float4 w = wih4[r * 128 + ec * 32 + eq];
#pragma unroll
            for (int jj = 0; jj < 8; jj++) {
                float4 f = fs[(bg * 8 + jj) * 32 + eq];
                acc[jj] += w.x * f.x + w.y * f.y + w.z * f.z + w.w * f.w;
            }
        }
    }
    float bias = b_ih[r] + b_hh[r];
#pragma unroll
    for (int jj = 0; jj < 8; jj++)
        g_gate_base[r * 64 + bg * 8 + jj] = acc[jj] + bias;
}

// ------------------------------------------------ LSTM S1: partial GEMM -----
// grid (128, 8): bx -> 8 hidden units (32 W rows), by -> k-split of 128.
// h stored [j][b]; partials [ks][r][b].
__global__ void __launch_bounds__(128)
lstm_part(const float4* __restrict__ whh4, int t) {
    const float4* hin4 = (const float4*)((t & 1) ? g_hB : g_hA);

    __shared__ float pool[1536];
    float* As = pool;          // [16][32]
    float* Bs = pool + 512;    // [16][64]
    float4* Bs4 = (float4*)Bs;

    int tid = threadIdx.x;
    int j0  = blockIdx.x * 8;
    int ks  = blockIdx.y;
    int kbase = ks * (KDIM / NSPLIT);      // 128 k per split
    int tx  = tid & 15;
    int ty  = tid >> 4;

    int lrl = tid >> 2;
    int lkq = tid & 3;
    int lr  = (lrl >> 3) * HID + j0 + (lrl & 7);

    float acc[4][4];
#pragma unroll
    for (int i = 0; i < 4; i++)
#pragma unroll
        for (int j = 0; j < 4; j++) acc[i][j] = 0.f;

    for (int kc = 0; kc < 8; kc++) {       // 8 chunks of 16 k
        int k0 = kbase + kc * 16;
        __syncthreads();
        {
            float4 v = whh4[lr * 256 + (k0 >> 2) + lkq];
            As[(lkq * 4 + 0) * 32 + lrl] = v.x;
            As[(lkq * 4 + 1) * 32 + lrl] = v.y;
            As[(lkq * 4 + 2) * 32 + lrl] = v.z;
            As[(lkq * 4 + 3) * 32 + lrl] = v.w;
        }
#pragma unroll
        for (int i = 0; i < 2; i++) {      // h[j][b]: 16 rows x 64 b
            int f = i * 128 + tid;
            int k = f >> 4, bq = f & 15;
            Bs4[k * 16 + bq] = hin4[(k0 + k) * 16 + bq];
        }
        __syncthreads();
#pragma unroll
        for (int kk = 0; kk < 16; kk++) {
            float4 a4 = *(const float4*)&As[kk * 32 + ty * 4];
            float4 b4 = *(const float4*)&Bs[kk * 64 + tx * 4];
            float a[4] = {a4.x, a4.y, a4.z, a4.w};
            float b[4] = {b4.x, b4.y, b4.z, b4.w};
#pragma unroll
            for (int i = 0; i < 4; i++)
#pragma unroll
                for (int j = 0; j < 4; j++) acc[i][j] += a[i] * b[j];
        }
    }
    // write partials: [ks][r][b], float4 along b
#pragma unroll
    for (int i = 0; i < 4; i++) {
        int rl = ty * 4 + i;
        int r  = (rl >> 3) * HID + j0 + (rl & 7);
        float4 v = make_float4(acc[i][0], acc[i][1], acc[i][2], acc[i][3]);
        *(float4*)&g_part[(size_t)(ks * G4 + r) * 64 + tx * 4] = v;
    }
}

// ------------------------------------------------ LSTM S2: reduce + fuse ----
// 256 blocks x 256 threads; thread = (j = bx*4 + tid>>6, b = tid&63)
__global__ void __launch_bounds__(256)
lstm_fuse(int t) {
    float* hout = (t & 1) ? g_hA : g_hB;
    int b = threadIdx.x & 63;
    int j = blockIdx.x * 4 + (threadIdx.x >> 6);

    float gate[4];
#pragma unroll
    for (int gi = 0; gi < 4; gi++) {
        int r = gi * HID + j;
        float s = g_gate_base[r * 64 + b];
#pragma unroll
        for (int ks = 0; ks < NSPLIT; ks++)
            s += g_part[(size_t)(ks * G4 + r) * 64 + b];
        gate[gi] = s;
    }
    float iv = 1.f / (1.f + expf(-gate[0]));
    float fv = 1.f / (1.f + expf(-gate[1]));
    float gv = tanhf(gate[2]);
    float ov = 1.f / (1.f + expf(-gate[3]));
    int ci = j * 64 + b;
    float c = fv * g_c[ci] + iv * gv;
    g_c[ci] = c;
    float h = ov * tanhf(c);
    hout[ci] = h;
    // emit GEMM A operand, m = b*TSTEPS + t
    int m = b * TSTEPS + t;
    __nv_bfloat16 hi = __float2bfloat16_rn(h);
    __nv_bfloat16 lo = __float2bfloat16_rn(h - __bfloat162float(hi));
    g_Ahi[(size_t)m * KDIM + j] = hi;
    g_Alo[(size_t)m * KDIM + j] = lo;
}

// ---------------------------------------- W_fc fp32 -> bf16 hi/lo -----------
__global__ void convW_kernel(const float4* __restrict__ w) {
    int n = blockIdx.x;
    int q = threadIdx.x;             // 0..255
    float4 v = w[(size_t)n * 256 + q];
    float x[4] = {v.x, v.y, v.z, v.w};
    __nv_bfloat16 hi[4], lo[4];
#pragma unroll
    for (int j = 0; j < 4; j++) {
        hi[j] = __float2bfloat16_rn(x[j]);
        lo[j] = __float2bfloat16_rn(x[j] - __bfloat162float(hi[j]));
    }
    uint32_t h01 = ((uint32_t)__bfloat16_as_ushort(hi[1]) << 16) | __bfloat16_as_ushort(hi[0]);
    uint32_t h23 = ((uint32_t)__bfloat16_as_ushort(hi[3]) << 16) | __bfloat16_as_ushort(hi[2]);
    uint32_t l01 = ((uint32_t)__bfloat16_as_ushort(lo[1]) << 16) | __bfloat16_as_ushort(lo[0]);
    uint32_t l23 = ((uint32_t)__bfloat16_as_ushort(lo[3]) << 16) | __bfloat16_as_ushort(lo[2]);
    ((uint2*)(g_Whi + (size_t)n * KDIM))[q] = make_uint2(h01, h23);
    ((uint2*)(g_Wlo + (size_t)n * KDIM))[q] = make_uint2(l01, l23);
}

// --------------------- vocab GEMM: fused 3-pass hi/lo, 128x256x32 -----------
#define BN      256
#define BK      32
#define NITER   (KDIM / BK)          // 32
#define APITCH  80                   // (32k * 2B) + 16 pad
#define A_T     (128 * APITCH)       // 10240 per half
#define B_T     (256 * APITCH)       // 20480 per half
#define STAGEB  (2 * A_T + 2 * B_T)  // 61440
#define NSTAGE  3
#define SMEMB   (NSTAGE * STAGEB)    // 184320

__device__ __forceinline__ void gemm_load(uint32_t sbase, int stage, int it,
                                          int tid, int m0, int n0) {
    int kk0 = it * BK;
    uint32_t sA = sbase + (uint32_t)stage * STAGEB;
    uint32_t sB = sA + 2 * A_T;
#pragma unroll
    for (int r = 0; r < 2; r++) {          // A: 1024 cp16 (hi+lo)
        int f = r * 512 + tid;
        int half = f >> 9, q4 = f & 511;
        int row = q4 >> 2, q = q4 & 3;
        const __nv_bfloat16* src = half ? g_Alo : g_Ahi;
        cp16(sA + (uint32_t)(half * A_T + row * APITCH + q * 16),
             src + (size_t)(m0 + row) * KDIM + kk0 + q * 8);
    }
#pragma unroll
    for (int r = 0; r < 4; r++) {          // B: 2048 cp16 (hi+lo)
        int f = r * 512 + tid;
        int half = f >> 10, q4 = f & 1023;
        int row = q4 >> 2, q = q4 & 3;
        int n = n0 + row;
        if (n > VOCAB - 1) n = VOCAB - 1;  // clamp: results discarded
        const __nv_bfloat16* src = half ? g_Wlo : g_Whi;
        cp16(sB + (uint32_t)(half * B_T + row * APITCH + q * 16),
             src + (size_t)n * KDIM + kk0 + q * 8);
    }
}

__global__ void __launch_bounds__(512, 1)
vocab_gemm_hmma(const float* __restrict__ b_fc, float* __restrict__ out) {
    extern __shared__ char sm[];
    uint32_t sbase = smem_u32(sm);
    int tid = threadIdx.x, lane = tid & 31, wid = tid >> 5;
    int wm = wid & 3, wn = wid >> 2;           // warp: 32(m) x 64(n)
    int m0 = blockIdx.x * 128;                 // 9 m-tiles fastest (B L2 reuse)
    int n0 = blockIdx.y * BN;                  // 197 n-tiles

    float acc[2][8][4];
#pragma unroll
    for (int i = 0; i < 2; i++)
#pragma unroll
        for (int j = 0; j < 8; j++)
#pragma unroll
            for (int k = 0; k < 4; k++) acc[i][j][k] = 0.f;

    gemm_load(sbase, 0, 0, tid, m0, n0); cp_commit();
    gemm_load(sbase, 1, 1, tid, m0, n0); cp_commit();

    for (int it = 0; it < NITER; it++) {
        cp_wait1();
        __syncthreads();
        if (it + 2 < NITER) gemm_load(sbase, (it + 2) % NSTAGE, it + 2, tid, m0, n0);
        cp_commit();

        uint32_t sA = sbase + (uint32_t)(it % NSTAGE) * STAGEB;
        uint32_t sB = sA + 2 * A_T;
#pragma unroll
        for (int kk = 0; kk < 2; kk++) {       // two k16 halves of BK=32
            uint32_t a_hi[2][4], a_lo[2][4];
#pragma unroll
            for (int mt = 0; mt < 2; mt++) {
                uint32_t arow = (uint32_t)((wm * 32 + mt * 16 + (lane & 15)) * APITCH
                                           + kk * 32 + (lane >> 4) * 16);
                ldsm4(a_hi[mt], sA + arow);
                ldsm4(a_lo[mt], sA + A_T + arow);
            }
#pragma unroll
            for (int bq = 0; bq < 4; bq++) {
                uint32_t b_hi[4], b_lo[4];
                int nrow = wn * 64 + bq * 16 + ((lane >> 4) << 3) + (lane & 7);
                uint32_t boff = (uint32_t)(nrow * APITCH + kk * 32 + ((lane >> 3) & 1) * 16);
                ldsm4(b_hi, sB + boff);
                ldsm4(b_lo, sB + B_T + boff);
#pragma unroll
                for (int mt = 0; mt < 2; mt++)
#pragma unroll
                    for (int s = 0; s < 2; s++) {
                        float* c = acc[mt][bq * 2 + s];
                        mma16816(c, a_hi[mt], &b_hi[s * 2]);   // hi*hi
                        mma16816(c, a_hi[mt], &b_lo[s * 2]);   // hi*lo
                        mma16816(c, a_lo[mt], &b_hi[s * 2]);   // lo*hi
                    }
            }
        }
        __syncthreads();
    }

#pragma unroll
    for (int mt = 0; mt < 2; mt++) {
        int r0 = m0 + wm * 32 + mt * 16 + (lane >> 2);
        float* o0 = out + (size_t)r0 * VOCAB;
        float* o1 = out + (size_t)(r0 + 8) * VOCAB;
#pragma unroll
        for (int nt = 0; nt < 8; nt++) {
            int col = n0 + wn * 64 + nt * 8 + (lane & 3) * 2;
            if (col < VOCAB) {
                float bz = b_fc[col];
                o0[col] = acc[mt][nt][0] + bz;
                o1[col] = acc[mt][nt][2] + bz;
            }
            if (col + 1 < VOCAB) {
                float bz = b_fc[col + 1];
                o0[col + 1] = acc[mt][nt][1] + bz;
                o1[col + 1] = acc[mt][nt][3] + bz;
            }
        }
    }
}

// ---------------------------------------------------------------------------
extern "C" void kernel_launch(void* const* d_in, const int* in_sizes, int n_in,
                              void* d_out, int out_size) {
    const float* features = (const float*)d_in[0];
    const float* W_ih     = (const float*)d_in[1];
    const float* W_hh     = (const float*)d_in[2];
    const float* b_ih     = (const float*)d_in[3];
    const float* b_hh     = (const float*)d_in[4];
    const float* W_fc     = (const float*)d_in[5];
    const float* b_fc     = (const float*)d_in[6];
    (void)in_sizes; (void)n_in; (void)out_size;

    cudaFuncSetAttribute(vocab_gemm_hmma,
                         cudaFuncAttributeMaxDynamicSharedMemorySize, SMEMB);

    init_kernel<<<(HID * BATCH + 255) / 256, 256>>>();
    xproj_kernel<<<128, 256>>>((const float4*)features, (const float4*)W_ih,
                               b_ih, b_hh);
    convW_kernel<<<VOCAB, 256>>>((const float4*)W_fc);

    for (int t = 0; t < TSTEPS; t++) {
        dim3 g1(128, NSPLIT);
        lstm_part<<<g1, 128>>>((const float4*)W_hh, t);
        lstm_fuse<<<256, 256>>>(t);
    }

    dim3 grid(MROWS / 128, (VOCAB + BN - 1) / BN);   // (9, 197)
    vocab_gemm_hmma<<<grid, 512, SMEMB>>>(b_fc, (float*)d_out);
}

// round 5
// speedup vs baseline: 3.7790x; 1.2520x over previous
#include <cuda_runtime.h>
#include <cuda_fp16.h>
#include <math.h>
#include <stdint.h>

#define BATCH  64
#define EMBED  512
#define HID    1024
#define G4     4096
#define VOCAB  50257
#define TSTEPS 18
#define MROWS  (BATCH*TSTEPS)   // 1152
#define KDIM   1024
#define NSPLIT 8                // LSTM k-splits

// ---------------- device scratch (static device globals; no allocs) ---------
__device__ float g_gate_base[G4 * BATCH];          // [r][b]
__device__ float g_hA[HID * BATCH];                // [j][b]
__device__ float g_hB[HID * BATCH];
__device__ float g_c [HID * BATCH];                // [j][b]
__device__ float g_part[NSPLIT * G4 * BATCH];      // [ks][r][b]  8 MB
__device__ __half g_Ah[MROWS * KDIM];              // [m][k] fp16   2.3 MB
__device__ __half g_Whi[(size_t)VOCAB * KDIM];     // 103 MB
__device__ __half g_Wlo[(size_t)VOCAB * KDIM];     // 103 MB

// ---------------------------------------------------------------- helpers ---
__device__ __forceinline__ uint32_t smem_u32(const void* p) {
    uint32_t a;
    asm("{ .reg .u64 t; cvta.to.shared.u64 t, %1; cvt.u32.u64 %0, t; }"
        : "=r"(a) : "l"(p));
    return a;
}
__device__ __forceinline__ void cp16(uint32_t s, const void* g) {
    asm volatile("cp.async.cg.shared.global [%0], [%1], 16;" :: "r"(s), "l"(g) : "memory");
}
__device__ __forceinline__ void cp_commit() {
    asm volatile("cp.async.commit_group;" ::: "memory");
}
__device__ __forceinline__ void cp_wait1() {
    asm volatile("cp.async.wait_group 1;" ::: "memory");
}
__device__ __forceinline__ void ldsm4(uint32_t* r, uint32_t a) {
    asm volatile("ldmatrix.sync.aligned.m8n8.x4.shared.b16 {%0,%1,%2,%3}, [%4];"
                 : "=r"(r[0]), "=r"(r[1]), "=r"(r[2]), "=r"(r[3]) : "r"(a));
}
__device__ __forceinline__ void mma16816(float* c, const uint32_t* a, const uint32_t* b) {
    asm volatile(
        "mma.sync.aligned.m16n8k16.row.col.f32.f16.f16.f32 "
        "{%0,%1,%2,%3},{%4,%5,%6,%7},{%8,%9},{%0,%1,%2,%3};"
        : "+f"(c[0]), "+f"(c[1]), "+f"(c[2]), "+f"(c[3])
        : "r"(a[0]), "r"(a[1]), "r"(a[2]), "r"(a[3]), "r"(b[0]), "r"(b[1]));
}

// ---------------------------------------------------------------- init ------
__global__ void init_kernel() {
    int i = blockIdx.x * blockDim.x + threadIdx.x;
    if (i < HID * BATCH) { g_hA[i] = 0.f; g_c[i] = 0.f; }
}

// ------------------------------------------------ x_proj = feat@W_ih^T + b --
__global__ void xproj_kernel(const float4* __restrict__ feat4,
                             const float4* __restrict__ wih4,
                             const float*  __restrict__ b_ih,
                             const float*  __restrict__ b_hh) {
    __shared__ float4 fs[BATCH * 32];
    int tid = threadIdx.x;
    int rl  = tid & 31;
    int bg  = tid >> 5;
    int r   = blockIdx.x * 32 + rl;
    float acc[8];
#pragma unroll
    for (int j = 0; j < 8; j++) acc[j] = 0.f;
    for (int ec = 0; ec < 4; ec++) {
        __syncthreads();
#pragma unroll
        for (int i = 0; i < 8; i++) {
            int lin = i * 256 + tid;
            int b = lin >> 5, q = lin & 31;
            fs[lin] = feat4[b * 128 + ec * 32 + q];
        }
        __syncthreads();
#pragma unroll 4
        for (int eq = 0; eq < 32; eq++) {
            float4 w = wih4[r * 128 + ec * 32 + eq];
#pragma unroll
            for (int jj = 0; jj < 8; jj++) {
                float4 f = fs[(bg * 8 + jj) * 32 + eq];
                acc[jj] += w.x * f.x + w.y * f.y + w.z * f.z + w.w * f.w;
            }
        }
    }
    float bias = b_ih[r] + b_hh[r];
#pragma unroll
    for (int jj = 0; jj < 8; jj++)
        g_gate_base[r * 64 + bg * 8 + jj] = acc[jj] + bias;
}

// ------------------------------------------------ LSTM S1: partial GEMM -----
__global__ void __launch_bounds__(128)
lstm_part(const float4* __restrict__ whh4, int t) {
    const float4* hin4 = (const float4*)((t & 1) ? g_hB : g_hA);

    __shared__ float pool[1536];
    float* As = pool;          // [16][32]
    float* Bs = pool + 512;    // [16][64]
    float4* Bs4 = (float4*)Bs;

    int tid = threadIdx.x;
    int j0  = blockIdx.x * 8;
    int ks  = blockIdx.y;
    int kbase = ks * (KDIM / NSPLIT);
    int tx  = tid & 15;
    int ty  = tid >> 4;

    int lrl = tid >> 2;
    int lkq = tid & 3;
    int lr  = (lrl >> 3) * HID + j0 + (lrl & 7);

    float acc[4][4];
#pragma unroll
    for (int i = 0; i < 4; i++)
#pragma unroll
        for (int j = 0; j < 4; j++) acc[i][j] = 0.f;

    for (int kc = 0; kc < 8; kc++) {
        int k0 = kbase + kc * 16;
        __syncthreads();
        {
            float4 v = whh4[lr * 256 + (k0 >> 2) + lkq];
            As[(lkq * 4 + 0) * 32 + lrl] = v.x;
            As[(lkq * 4 + 1) * 32 + lrl] = v.y;
            As[(lkq * 4 + 2) * 32 + lrl] = v.z;
            As[(lkq * 4 + 3) * 32 + lrl] = v.w;
        }
#pragma unroll
        for (int i = 0; i < 2; i++) {
            int f = i * 128 + tid;
            int k = f >> 4, bq = f & 15;
            Bs4[k * 16 + bq] = hin4[(k0 + k) * 16 + bq];
        }
        __syncthreads();
#pragma unroll
        for (int kk = 0; kk < 16; kk++) {
            float4 a4 = *(const float4*)&As[kk * 32 + ty * 4];
            float4 b4 = *(const float4*)&Bs[kk * 64 + tx * 4];
            float a[4] = {a4.x, a4.y, a4.z, a4.w};
            float b[4] = {b4.x, b4.y, b4.z, b4.w};
#pragma unroll
            for (int i = 0; i < 4; i++)
#pragma unroll
                for (int j = 0; j < 4; j++) acc[i][j] += a[i] * b[j];
        }
    }
#pragma unroll
    for (int i = 0; i < 4; i++) {
        int rl = ty * 4 + i;
        int r  = (rl >> 3) * HID + j0 + (rl & 7);
        float4 v = make_float4(acc[i][0], acc[i][1], acc[i][2], acc[i][3]);
        *(float4*)&g_part[(size_t)(ks * G4 + r) * 64 + tx * 4] = v;
    }
}

// ------------------------------------------------ LSTM S2: reduce + fuse ----
__global__ void __launch_bounds__(256)
lstm_fuse(int t) {
    float* hout = (t & 1) ? g_hA : g_hB;
    int b = threadIdx.x & 63;
    int j = blockIdx.x * 4 + (threadIdx.x >> 6);

    float gate[4];
#pragma unroll
    for (int gi = 0; gi < 4; gi++) {
        int r = gi * HID + j;
        float s = g_gate_base[r * 64 + b];
#pragma unroll
        for (int ks = 0; ks < NSPLIT; ks++)
            s += g_part[(size_t)(ks * G4 + r) * 64 + b];
        gate[gi] = s;
    }
    float iv = 1.f / (1.f + expf(-gate[0]));
    float fv = 1.f / (1.f + expf(-gate[1]));
    float gv = tanhf(gate[2]);
    float ov = 1.f / (1.f + expf(-gate[3]));
    int ci = j * 64 + b;
    float c = fv * g_c[ci] + iv * gv;
    g_c[ci] = c;
    float h = ov * tanhf(c);
    hout[ci] = h;
    int m = b * TSTEPS + t;
    g_Ah[(size_t)m * KDIM + j] = __float2half_rn(h);
}

// ---------------------------------------- W_fc fp32 -> fp16 hi/lo -----------
__global__ void convW_kernel(const float4* __restrict__ w) {
    int n = blockIdx.x;
    int q = threadIdx.x;             // 0..255
    float4 v = w[(size_t)n * 256 + q];
    float x[4] = {v.x, v.y, v.z, v.w};
    __half hi[4], lo[4];
#pragma unroll
    for (int j = 0; j < 4; j++) {
        hi[j] = __float2half_rn(x[j]);
        lo[j] = __float2half_rn(x[j] - __half2float(hi[j]));
    }
    uint32_t h01 = ((uint32_t)__half_as_ushort(hi[1]) << 16) | __half_as_ushort(hi[0]);
    uint32_t h23 = ((uint32_t)__half_as_ushort(hi[3]) << 16) | __half_as_ushort(hi[2]);
    uint32_t l01 = ((uint32_t)__half_as_ushort(lo[1]) << 16) | __half_as_ushort(lo[0]);
    uint32_t l23 = ((uint32_t)__half_as_ushort(lo[3]) << 16) | __half_as_ushort(lo[2]);
    ((uint2*)(g_Whi + (size_t)n * KDIM))[q] = make_uint2(h01, h23);
    ((uint2*)(g_Wlo + (size_t)n * KDIM))[q] = make_uint2(l01, l23);
}

// --------------------- vocab GEMM: fp16 2-pass, 128x256x64, 2-stage ---------
#define BN      256
#define BK      64
#define NITER   (KDIM / BK)          // 16
#define APITCH  144                  // 64k*2B + 16 pad
#define A_T     (128 * APITCH)       // 18432 (A hi only)
#define B_T     (256 * APITCH)       // 36864 per half
#define STAGEB  (A_T + 2 * B_T)      // 92160
#define NSTAGE  2
#define SMEMB   (NSTAGE * STAGEB)    // 184320

__device__ __forceinline__ void gemm_load(uint32_t sbase, int stage, int it,
                                          int tid, int m0, int n0) {
    int kk0 = it * BK;
    uint32_t sA = sbase + (uint32_t)stage * STAGEB;
    uint32_t sB = sA + A_T;
#pragma unroll
    for (int r = 0; r < 2; r++) {          // A: 1024 cp16
        int f = r * 512 + tid;
        int row = f >> 3, q = f & 7;
        cp16(sA + (uint32_t)(row * APITCH + q * 16),
             g_Ah + (size_t)(m0 + row) * KDIM + kk0 + q * 8);
    }
#pragma unroll
    for (int r = 0; r < 8; r++) {          // B: 4096 cp16 (hi+lo)
        int f = r * 512 + tid;
        int half = f >> 11, q8 = f & 2047;
        int row = q8 >> 3, q = q8 & 7;
        int n = n0 + row;
        if (n > VOCAB - 1) n = VOCAB - 1;  // clamp: results discarded
        const __half* src = half ? g_Wlo : g_Whi;
        cp16(sB + (uint32_t)(half * B_T + row * APITCH + q * 16),
             src + (size_t)n * KDIM + kk0 + q * 8);
    }
}

__global__ void __launch_bounds__(512, 1)
vocab_gemm_hmma(const float* __restrict__ b_fc, float* __restrict__ out) {
    extern __shared__ char sm[];
    uint32_t sbase = smem_u32(sm);
    int tid = threadIdx.x, lane = tid & 31, wid = tid >> 5;
    int wm = wid & 3, wn = wid >> 2;           // warp: 32(m) x 64(n)
    int m0 = blockIdx.x * 128;                 // 9 m-tiles fastest (B L2 reuse)
    int n0 = blockIdx.y * BN;                  // 197 n-tiles

    float acc[2][8][4];
#pragma unroll
    for (int i = 0; i < 2; i++)
#pragma unroll
        for (int j = 0; j < 8; j++)
#pragma unroll
            for (int k = 0; k < 4; k++) acc[i][j][k] = 0.f;

    gemm_load(sbase, 0, 0, tid, m0, n0);
    cp_commit();

    for (int it = 0; it < NITER; it++) {
        if (it + 1 < NITER) {
            gemm_load(sbase, (it + 1) & 1, it + 1, tid, m0, n0);
            cp_commit();
            cp_wait1();                        // stage `it` ready; it+1 in flight
        } else {
            asm volatile("cp.async.wait_group 0;" ::: "memory");
        }
        __syncthreads();

        uint32_t sA = sbase + (uint32_t)(it & 1) * STAGEB;
        uint32_t sB = sA + A_T;
#pragma unroll
        for (int kk = 0; kk < 4; kk++) {       // four k16 slices of BK=64
            uint32_t a[2][4];
#pragma unroll
            for (int mt = 0; mt < 2; mt++)
                ldsm4(a[mt], sA + (uint32_t)((wm * 32 + mt * 16 + (lane & 15)) * APITCH
                                             + kk * 32 + (lane >> 4) * 16));
#pragma unroll
            for (int bq = 0; bq < 4; bq++) {
                uint32_t b_hi[4], b_lo[4];
                int nrow = wn * 64 + bq * 16 + ((lane >> 4) << 3) + (lane & 7);
                uint32_t boff = (uint32_t)(nrow * APITCH + kk * 32 + ((lane >> 3) & 1) * 16);
                ldsm4(b_hi, sB + boff);
                ldsm4(b_lo, sB + B_T + boff);
#pragma unroll
                for (int mt = 0; mt < 2; mt++)
#pragma unroll
                    for (int s = 0; s < 2; s++) {
                        float* c = acc[mt][bq * 2 + s];
                        mma16816(c, a[mt], &b_hi[s * 2]);   // A * Bhi
                        mma16816(c, a[mt], &b_lo[s * 2]);   // A * Blo
                    }
            }
        }
        __syncthreads();
    }

#pragma unroll
    for (int mt = 0; mt < 2; mt++) {
        int r0 = m0 + wm * 32 + mt * 16 + (lane >> 2);
        float* o0 = out + (size_t)r0 * VOCAB;
        float* o1 = out + (size_t)(r0 + 8) * VOCAB;
#pragma unroll
        for (int nt = 0; nt < 8; nt++) {
            int col = n0 + wn * 64 + nt * 8 + (lane & 3) * 2;
            if (col < VOCAB) {
                float bz = b_fc[col];
                o0[col] = acc[mt][nt][0] + bz;
                o1[col] = acc[mt][nt][2] + bz;
            }
            if (col + 1 < VOCAB) {
                float bz = b_fc[col + 1];
                o0[col + 1] = acc[mt][nt][1] + bz;
                o1[col + 1] = acc[mt][nt][3] + bz;
            }
        }
    }
}

// ---------------------------------------------------------------------------
extern "C" void kernel_launch(void* const* d_in, const int* in_sizes, int n_in,
                              void* d_out, int out_size) {
    const float* features = (const float*)d_in[0];
    const float* W_ih     = (const float*)d_in[1];
    const float* W_hh     = (const float*)d_in[2];
    const float* b_ih     = (const float*)d_in[3];
    const float* b_hh     = (const float*)d_in[4];
    const float* W_fc     = (const float*)d_in[5];
    const float* b_fc     = (const float*)d_in[6];
    (void)in_sizes; (void)n_in; (void)out_size;

    cudaFuncSetAttribute(vocab_gemm_hmma,
                         cudaFuncAttributeMaxDynamicSharedMemorySize, SMEMB);

    init_kernel<<<(HID * BATCH + 255) / 256, 256>>>();
    xproj_kernel<<<128, 256>>>((const float4*)features, (const float4*)W_ih,
                               b_ih, b_hh);
    convW_kernel<<<VOCAB, 256>>>((const float4*)W_fc);

    for (int t = 0; t < TSTEPS; t++) {
        dim3 g1(128, NSPLIT);
        lstm_part<<<g1, 128>>>((const float4*)W_hh, t);
        lstm_fuse<<<256, 256>>>(t);
    }

    dim3 grid(MROWS / 128, (VOCAB + BN - 1) / BN);   // (9, 197)
    vocab_gemm_hmma<<<grid, 512, SMEMB>>>(b_fc, (float*)d_out);
}

// round 6
// speedup vs baseline: 4.2545x; 1.1258x over previous
#include <cuda_runtime.h>
#include <cuda_fp16.h>
#include <cuda_bf16.h>
#include <math.h>
#include <stdint.h>

#define BATCH  64
#define EMBED  512
#define HID    1024
#define G4     4096
#define VOCAB  50257
#define TSTEPS 18
#define MROWS  (BATCH*TSTEPS)   // 1152
#define KDIM   1024
#define NSPLIT 2                // LSTM k-splits (512 K each)

// ---------------- device scratch (static device globals; no allocs) ---------
__device__ float g_gate_base[BATCH * G4];            // [b][r]
__device__ float g_c[BATCH * HID];                   // [b][j]
__device__ float g_part[NSPLIT * BATCH * G4];        // [ks][b][r]  2 MB
__device__ __nv_bfloat16 g_hhi[BATCH * HID];         // recurrence A hi [b][j]
__device__ __nv_bfloat16 g_hlo[BATCH * HID];         // recurrence A lo
__device__ __nv_bfloat16 g_whh_hi[G4 * KDIM];        // 8 MB
__device__ __nv_bfloat16 g_whh_lo[G4 * KDIM];        // 8 MB
__device__ __half g_Ah[MROWS * KDIM];                // vocab A fp16  2.3 MB
__device__ __half g_Whi[(size_t)VOCAB * KDIM];       // 103 MB
__device__ __half g_Wlo[(size_t)VOCAB * KDIM];       // 103 MB

// ---------------------------------------------------------------- helpers ---
__device__ __forceinline__ uint32_t smem_u32(const void* p) {
    uint32_t a;
    asm("{ .reg .u64 t; cvta.to.shared.u64 t, %1; cvt.u32.u64 %0, t; }"
        : "=r"(a) : "l"(p));
    return a;
}
__device__ __forceinline__ void cp16(uint32_t s, const void* g) {
    asm volatile("cp.async.cg.shared.global [%0], [%1], 16;" :: "r"(s), "l"(g) : "memory");
}
__device__ __forceinline__ void cp_commit() {
    asm volatile("cp.async.commit_group;" ::: "memory");
}
__device__ __forceinline__ void cp_wait1() {
    asm volatile("cp.async.wait_group 1;" ::: "memory");
}
__device__ __forceinline__ void cp_wait0() {
    asm volatile("cp.async.wait_group 0;" ::: "memory");
}
__device__ __forceinline__ void ldsm4(uint32_t* r, uint32_t a) {
    asm volatile("ldmatrix.sync.aligned.m8n8.x4.shared.b16 {%0,%1,%2,%3}, [%4];"
                 : "=r"(r[0]), "=r"(r[1]), "=r"(r[2]), "=r"(r[3]) : "r"(a));
}
__device__ __forceinline__ void mma_fp16(float* c, const uint32_t* a, const uint32_t* b) {
    asm volatile(
        "mma.sync.aligned.m16n8k16.row.col.f32.f16.f16.f32 "
        "{%0,%1,%2,%3},{%4,%5,%6,%7},{%8,%9},{%0,%1,%2,%3};"
        : "+f"(c[0]), "+f"(c[1]), "+f"(c[2]), "+f"(c[3])
        : "r"(a[0]), "r"(a[1]), "r"(a[2]), "r"(a[3]), "r"(b[0]), "r"(b[1]));
}
__device__ __forceinline__ void mma_bf16(float* c, const uint32_t* a, const uint32_t* b) {
    asm volatile(
        "mma.sync.aligned.m16n8k16.row.col.f32.bf16.bf16.f32 "
        "{%0,%1,%2,%3},{%4,%5,%6,%7},{%8,%9},{%0,%1,%2,%3};"
        : "+f"(c[0]), "+f"(c[1]), "+f"(c[2]), "+f"(c[3])
        : "r"(a[0]), "r"(a[1]), "r"(a[2]), "r"(a[3]), "r"(b[0]), "r"(b[1]));
}

// ---------------------------------------------------------------- init ------
__global__ void init_kernel() {
    int i = blockIdx.x * blockDim.x + threadIdx.x;
    if (i < BATCH * HID) {
        g_c[i] = 0.f;
        g_hhi[i] = __float2bfloat16(0.f);
        g_hlo[i] = __float2bfloat16(0.f);
    }
}

// ------------------------------------------------ x_proj -> gate_base[b][r] -
__global__ void xproj_kernel(const float4* __restrict__ feat4,
                             const float4* __restrict__ wih4,
                             const float*  __restrict__ b_ih,
                             const float*  __restrict__ b_hh) {
    __shared__ float4 fs[BATCH * 32];
    int tid = threadIdx.x;
    int rl  = tid & 31;
    int bg  = tid >> 5;
    int r   = blockIdx.x * 32 + rl;
    float acc[8];
#pragma unroll
    for (int j = 0; j < 8; j++) acc[j] = 0.f;
    for (int ec = 0; ec < 4; ec++) {
        __syncthreads();
#pragma unroll
        for (int i = 0; i < 8; i++) {
            int lin = i * 256 + tid;
            int b = lin >> 5, q = lin & 31;
            fs[lin] = feat4[b * 128 + ec * 32 + q];
        }
        __syncthreads();
#pragma unroll 4
        for (int eq = 0; eq < 32; eq++) {
            float4 w = wih4[r * 128 + ec * 32 + eq];
#pragma unroll
            for (int jj = 0; jj < 8; jj++) {
                float4 f = fs[(bg * 8 + jj) * 32 + eq];
                acc[jj] += w.x * f.x + w.y * f.y + w.z * f.z + w.w * f.w;
            }
        }
    }
    float bias = b_ih[r] + b_hh[r];
#pragma unroll
    for (int jj = 0; jj < 8; jj++)
        g_gate_base[(bg * 8 + jj) * G4 + r] = acc[jj] + bias;
}

// ---------------------------------------- W_fc fp32 -> fp16 hi/lo -----------
__global__ void convW_kernel(const float4* __restrict__ w) {
    int n = blockIdx.x;
    int q = threadIdx.x;
    float4 v = w[(size_t)n * 256 + q];
    float x[4] = {v.x, v.y, v.z, v.w};
    __half hi[4], lo[4];
#pragma unroll
    for (int j = 0; j < 4; j++) {
        hi[j] = __float2half_rn(x[j]);
        lo[j] = __float2half_rn(x[j] - __half2float(hi[j]));
    }
    uint32_t h01 = ((uint32_t)__half_as_ushort(hi[1]) << 16) | __half_as_ushort(hi[0]);
    uint32_t h23 = ((uint32_t)__half_as_ushort(hi[3]) << 16) | __half_as_ushort(hi[2]);
    uint32_t l01 = ((uint32_t)__half_as_ushort(lo[1]) << 16) | __half_as_ushort(lo[0]);
    uint32_t l23 = ((uint32_t)__half_as_ushort(lo[3]) << 16) | __half_as_ushort(lo[2]);
    ((uint2*)(g_Whi + (size_t)n * KDIM))[q] = make_uint2(h01, h23);
    ((uint2*)(g_Wlo + (size_t)n * KDIM))[q] = make_uint2(l01, l23);
}

// ---------------------------------------- W_hh fp32 -> bf16 hi/lo -----------
__global__ void convWhh_kernel(const float4* __restrict__ w) {
    int n = blockIdx.x;              // 0..4095
    int q = threadIdx.x;             // 0..255
    float4 v = w[(size_t)n * 256 + q];
    float x[4] = {v.x, v.y, v.z, v.w};
    __nv_bfloat16 hi[4], lo[4];
#pragma unroll
    for (int j = 0; j < 4; j++) {
        hi[j] = __float2bfloat16_rn(x[j]);
        lo[j] = __float2bfloat16_rn(x[j] - __bfloat162float(hi[j]));
    }
    uint32_t h01 = ((uint32_t)__bfloat16_as_ushort(hi[1]) << 16) | __bfloat16_as_ushort(hi[0]);
    uint32_t h23 = ((uint32_t)__bfloat16_as_ushort(hi[3]) << 16) | __bfloat16_as_ushort(hi[2]);
    uint32_t l01 = ((uint32_t)__bfloat16_as_ushort(lo[1]) << 16) | __bfloat16_as_ushort(lo[0]);
    uint32_t l23 = ((uint32_t)__bfloat16_as_ushort(lo[3]) << 16) | __bfloat16_as_ushort(lo[2]);
    ((uint2*)(g_whh_hi + (size_t)n * KDIM))[q] = make_uint2(h01, h23);
    ((uint2*)(g_whh_lo + (size_t)n * KDIM))[q] = make_uint2(l01, l23);
}

// --------------------- LSTM S1: h @ Whh^T on tensor cores (bf16 3-pass) -----
// grid (64, NSPLIT): n0 = bx*64 (W rows), ks k-chunk of 512.
// block 128 (4 warps), warp 32m x 32n. 2-stage cp.async, BK=64.
#define RPITCH  144                   // 64k*2B + 16
#define R_HALF  (64 * RPITCH)         // 9216
#define R_AT    (2 * R_HALF)          // A hi+lo
#define R_BT    (2 * R_HALF)
#define R_STAGE (R_AT + R_BT)         // 36864
#define R_SMEM  (2 * R_STAGE)         // 73728

__device__ __forceinline__ void rec_load(uint32_t sbase, int stage, int it,
                                         int tid, int n0, int kbase) {
    int k0 = kbase + it * 64;
    uint32_t sA = sbase + (uint32_t)stage * R_STAGE;
    uint32_t sB = sA + R_AT;
#pragma unroll
    for (int r = 0; r < 8; r++) {          // A: 1024 cp16 (hi+lo)
        int f = r * 128 + tid;
        int half = f >> 9, q = f & 511;
        int row = q >> 3, qq = q & 7;
        const __nv_bfloat16* src = half ? g_hlo : g_hhi;
        cp16(sA + (uint32_t)(half * R_HALF + row * RPITCH + qq * 16),
             src + (size_t)row * KDIM + k0 + qq * 8);
    }
#pragma unroll
    for (int r = 0; r < 8; r++) {          // B: 1024 cp16 (hi+lo)
        int f = r * 128 + tid;
        int half = f >> 9, q = f & 511;
        int row = q >> 3, qq = q & 7;
        const __nv_bfloat16* src = half ? g_whh_lo : g_whh_hi;
        cp16(sB + (uint32_t)(half * R_HALF + row * RPITCH + qq * 16),
             src + (size_t)(n0 + row) * KDIM + k0 + qq * 8);
    }
}

__global__ void __launch_bounds__(128)
lstm_mma(int t) {
    extern __shared__ char sm[];
    uint32_t sbase = smem_u32(sm);
    int tid = threadIdx.x, lane = tid & 31, wid = tid >> 5;
    int wm = wid & 1, wn = wid >> 1;       // warp: 32m x 32n
    int n0 = blockIdx.x * 64;
    int ks = blockIdx.y;
    int kbase = ks * (KDIM / NSPLIT);

    float acc[2][4][4];
#pragma unroll
    for (int i = 0; i < 2; i++)
#pragma unroll
        for (int j = 0; j < 4; j++)
#pragma unroll
            for (int k = 0; k < 4; k++) acc[i][j][k] = 0.f;

    rec_load(sbase, 0, 0, tid, n0, kbase);
    cp_commit();

    const int NIT = (KDIM / NSPLIT) / 64;  // 8
    for (int it = 0; it < NIT; it++) {
        if (it + 1 < NIT) {
            rec_load(sbase, (it + 1) & 1, it + 1, tid, n0, kbase);
            cp_commit();
            cp_wait1();
        } else {
            cp_wait0();
        }
        __syncthreads();
        uint32_t sA = sbase + (uint32_t)(it & 1) * R_STAGE;
        uint32_t sB = sA + R_AT;
#pragma unroll
        for (int kk = 0; kk < 4; kk++) {
            uint32_t a_hi[2][4], a_lo[2][4];
#pragma unroll
            for (int mt = 0; mt < 2; mt++) {
                uint32_t arow = (uint32_t)((wm * 32 + mt * 16 + (lane & 15)) * RPITCH
                                           + kk * 32 + (lane >> 4) * 16);
                ldsm4(a_hi[mt], sA + arow);
                ldsm4(a_lo[mt], sA + R_HALF + arow);
            }
#pragma unroll
            for (int bq = 0; bq < 2; bq++) {
                uint32_t b_hi[4], b_lo[4];
                int nrow = wn * 32 + bq * 16 + ((lane >> 4) << 3) + (lane & 7);
                uint32_t boff = (uint32_t)(nrow * RPITCH + kk * 32 + ((lane >> 3) & 1) * 16);
                ldsm4(b_hi, sB + boff);
                ldsm4(b_lo, sB + R_HALF + boff);
#pragma unroll
                for (int mt = 0; mt < 2; mt++)
#pragma unroll
                    for (int s = 0; s < 2; s++) {
                        float* c = acc[mt][bq * 2 + s];
                        mma_bf16(c, a_hi[mt], &b_hi[s * 2]);   // hi*hi
                        mma_bf16(c, a_hi[mt], &b_lo[s * 2]);   // hi*lo
                        mma_bf16(c, a_lo[mt], &b_hi[s * 2]);   // lo*hi
                    }
            }
        }
        __syncthreads();
    }
    // partials: [ks][b][r]
    float* base = g_part + (size_t)ks * BATCH * G4;
#pragma unroll
    for (int mt = 0; mt < 2; mt++) {
        int m = wm * 32 + mt * 16 + (lane >> 2);
#pragma unroll
        for (int nt = 0; nt < 4; nt++) {
            int n = n0 + wn * 32 + nt * 8 + (lane & 3) * 2;
            *(float2*)&base[(size_t)m * G4 + n] =
                make_float2(acc[mt][nt][0], acc[mt][nt][1]);
            *(float2*)&base[(size_t)(m + 8) * G4 + n] =
                make_float2(acc[mt][nt][2], acc[mt][nt][3]);
        }
    }
}

// ------------------------------------------------ LSTM S2: reduce + fuse ----
// grid (4, 64), block 256: j = bx*256+tid, b = by. All accesses coalesced in j.
__global__ void __launch_bounds__(256)
lstm_fuse(int t) {
    int j = blockIdx.x * 256 + threadIdx.x;
    int b = blockIdx.y;

    float gate[4];
#pragma unroll
    for (int gi = 0; gi < 4; gi++) {
        int r = gi * HID + j;
        gate[gi] = g_gate_base[(size_t)b * G4 + r]
                 + g_part[(size_t)b * G4 + r]
                 + g_part[(size_t)(BATCH + b) * G4 + r];
    }
    float iv = 1.f / (1.f + expf(-gate[0]));
    float fv = 1.f / (1.f + expf(-gate[1]));
    float gv = tanhf(gate[2]);
    float ov = 1.f / (1.f + expf(-gate[3]));
    int ci = b * HID + j;
    float c = fv * g_c[ci] + iv * gv;
    g_c[ci] = c;
    float h = ov * tanhf(c);
    __nv_bfloat16 hi = __float2bfloat16_rn(h);
    g_hhi[ci] = hi;
    g_hlo[ci] = __float2bfloat16_rn(h - __bfloat162float(hi));
    g_Ah[(size_t)(b * TSTEPS + t) * KDIM + j] = __float2half_rn(h);
}

// --------------------- vocab GEMM: fp16 2-pass, 128x256x32, 3-stage ---------
#define BN      256
#define BK      32
#define NITER   (KDIM / BK)          // 32
#define APITCH  80                   // 32k*2B + 16 pad
#define A_T     (128 * APITCH)       // 10240 (A hi only)
#define B_T     (256 * APITCH)       // 20480 per half
#define STAGEB  (A_T + 2 * B_T)      // 51200
#define NSTAGE  3
#define SMEMB   (NSTAGE * STAGEB)    // 153600

__device__ __forceinline__ void gemm_load(uint32_t sbase, int stage, int it,
                                          int tid, int m0, int n0) {
    int kk0 = it * BK;
    uint32_t sA = sbase + (uint32_t)stage * STAGEB;
    uint32_t sB = sA + A_T;
    {                                       // A: 512 cp16
        int row = tid >> 2, q = tid & 3;
        cp16(sA + (uint32_t)(row * APITCH + q * 16),
             g_Ah + (size_t)(m0 + row) * KDIM + kk0 + q * 8);
    }
#pragma unroll
    for (int r = 0; r < 4; r++) {           // B: 2048 cp16 (hi+lo)
        int f = r * 512 + tid;
        int half = f >> 10, q8 = f & 1023;
        int row = q8 >> 2, q = q8 & 3;
        int n = n0 + row;
        if (n > VOCAB - 1) n = VOCAB - 1;   // clamp: results discarded
        const __half* src = half ? g_Wlo : g_Whi;
        cp16(sB + (uint32_t)(half * B_T + row * APITCH + q * 16),
             src + (size_t)n * KDIM + kk0 + q * 8);
    }
}

__global__ void __launch_bounds__(512, 1)
vocab_gemm_hmma(const float* __restrict__ b_fc, float* __restrict__ out) {
    extern __shared__ char sm[];
    uint32_t sbase = smem_u32(sm);
    int tid = threadIdx.x, lane = tid & 31, wid = tid >> 5;
    int wm = wid & 3, wn = wid >> 2;           // warp: 32(m) x 64(n)
    int m0 = blockIdx.x * 128;
    int n0 = blockIdx.y * BN;

    float acc[2][8][4];
#pragma unroll
    for (int i = 0; i < 2; i++)
#pragma unroll
        for (int j = 0; j < 8; j++)
#pragma unroll
            for (int k = 0; k < 4; k++) acc[i][j][k] = 0.f;

    gemm_load(sbase, 0, 0, tid, m0, n0); cp_commit();
    gemm_load(sbase, 1, 1, tid, m0, n0); cp_commit();

    for (int it = 0; it < NITER; it++) {
        cp_wait1();
        __syncthreads();
        if (it + 2 < NITER) gemm_load(sbase, (it + 2) % NSTAGE, it + 2, tid, m0, n0);
        cp_commit();

        uint32_t sA = sbase + (uint32_t)(it % NSTAGE) * STAGEB;
        uint32_t sB = sA + A_T;
#pragma unroll
        for (int kk = 0; kk < 2; kk++) {
            uint32_t a[2][4];
#pragma unroll
            for (int mt = 0; mt < 2; mt++)
                ldsm4(a[mt], sA + (uint32_t)((wm * 32 + mt * 16 + (lane & 15)) * APITCH
                                             + kk * 32 + (lane >> 4) * 16));
#pragma unroll
            for (int bq = 0; bq < 4; bq++) {
                uint32_t b_hi[4], b_lo[4];
                int nrow = wn * 64 + bq * 16 + ((lane >> 4) << 3) + (lane & 7);
                uint32_t boff = (uint32_t)(nrow * APITCH + kk * 32 + ((lane >> 3) & 1) * 16);
                ldsm4(b_hi, sB + boff);
                ldsm4(b_lo, sB + B_T + boff);
#pragma unroll
                for (int mt = 0; mt < 2; mt++)
#pragma unroll
                    for (int s = 0; s < 2; s++) {
                        float* c = acc[mt][bq * 2 + s];
                        mma_fp16(c, a[mt], &b_hi[s * 2]);   // A * Bhi
                        mma_fp16(c, a[mt], &b_lo[s * 2]);   // A * Blo
                    }
            }
        }
        __syncthreads();
    }

#pragma unroll
    for (int mt = 0; mt < 2; mt++) {
        int r0 = m0 + wm * 32 + mt * 16 + (lane >> 2);
        float* o0 = out + (size_t)r0 * VOCAB;
        float* o1 = out + (size_t)(r0 + 8) * VOCAB;
#pragma unroll
        for (int nt = 0; nt < 8; nt++) {
            int col = n0 + wn * 64 + nt * 8 + (lane & 3) * 2;
            if (col < VOCAB) {
                float bz = b_fc[col];
                o0[col] = acc[mt][nt][0] + bz;
                o1[col] = acc[mt][nt][2] + bz;
            }
            if (col + 1 < VOCAB) {
                float bz = b_fc[col + 1];
                o0[col + 1] = acc[mt][nt][1] + bz;
                o1[col + 1] = acc[mt][nt][3] + bz;
            }
        }
    }
}

// ---------------------------------------------------------------------------
extern "C" void kernel_launch(void* const* d_in, const int* in_sizes, int n_in,
                              void* d_out, int out_size) {
    const float* features = (const float*)d_in[0];
    const float* W_ih     = (const float*)d_in[1];
    const float* W_hh     = (const float*)d_in[2];
    const float* b_ih     = (const float*)d_in[3];
    const float* b_hh     = (const float*)d_in[4];
    const float* W_fc     = (const float*)d_in[5];
    const float* b_fc     = (const float*)d_in[6];
    (void)in_sizes; (void)n_in; (void)out_size;

    cudaFuncSetAttribute(vocab_gemm_hmma,
                         cudaFuncAttributeMaxDynamicSharedMemorySize, SMEMB);
    cudaFuncSetAttribute(lstm_mma,
                         cudaFuncAttributeMaxDynamicSharedMemorySize, R_SMEM);

    init_kernel<<<(BATCH * HID + 255) / 256, 256>>>();
    xproj_kernel<<<128, 256>>>((const float4*)features, (const float4*)W_ih,
                               b_ih, b_hh);
    convW_kernel<<<VOCAB, 256>>>((const float4*)W_fc);
    convWhh_kernel<<<G4, 256>>>((const float4*)W_hh);   // last: leaves W_hh L2-warm

    for (int t = 0; t < TSTEPS; t++) {
        dim3 g1(64, NSPLIT);
        lstm_mma<<<g1, 128, R_SMEM>>>(t);
        dim3 g2(4, BATCH);
        lstm_fuse<<<g2, 256>>>(t);
    }

    dim3 grid(MROWS / 128, (VOCAB + BN - 1) / BN);   // (9, 197)
    vocab_gemm_hmma<<<grid, 512, SMEMB>>>(b_fc, (float*)d_out);
}

// round 7
// speedup vs baseline: 4.7813x; 1.1238x over previous
#include <cuda_runtime.h>
#include <cuda_fp16.h>
#include <cuda_bf16.h>
#include <math.h>
#include <stdint.h>

#define BATCH  64
#define EMBED  512
#define HID    1024
#define G4     4096
#define VOCAB  50257
#define TSTEPS 18
#define MROWS  (BATCH*TSTEPS)   // 1152
#define KDIM   1024

// ---------------- device scratch (static device globals; no allocs) ---------
__device__ float g_gate_base[BATCH * G4];            // [b][p]  (permuted rows)
__device__ float g_c[BATCH * HID];                   // [b][j]
__device__ __nv_bfloat16 g_hhi[BATCH * HID];         // recurrence A hi [b][j]
__device__ __nv_bfloat16 g_hlo[BATCH * HID];         // recurrence A lo
__device__ __nv_bfloat16 g_whh_hi[G4 * KDIM];        // permuted rows, 8 MB
__device__ __nv_bfloat16 g_whh_lo[G4 * KDIM];        // 8 MB
__device__ __half g_Ah[MROWS * KDIM];                // vocab A fp16  2.3 MB
__device__ __half g_Whi[(size_t)VOCAB * KDIM];       // 103 MB

// permuted row index: r = gi*HID + j  ->  p = (j>>4)*64 + gi*16 + (j&15)
__device__ __forceinline__ int perm_row(int r) {
    int gi = r >> 10, j = r & (HID - 1);
    return ((j >> 4) << 6) + (gi << 4) + (j & 15);
}

// ---------------------------------------------------------------- helpers ---
__device__ __forceinline__ uint32_t smem_u32(const void* p) {
    uint32_t a;
    asm("{ .reg .u64 t; cvta.to.shared.u64 t, %1; cvt.u32.u64 %0, t; }"
        : "=r"(a) : "l"(p));
    return a;
}
__device__ __forceinline__ void cp16(uint32_t s, const void* g) {
    asm volatile("cp.async.cg.shared.global [%0], [%1], 16;" :: "r"(s), "l"(g) : "memory");
}
__device__ __forceinline__ void cp_commit() {
    asm volatile("cp.async.commit_group;" ::: "memory");
}
__device__ __forceinline__ void cp_wait1() {
    asm volatile("cp.async.wait_group 1;" ::: "memory");
}
__device__ __forceinline__ void cp_wait0() {
    asm volatile("cp.async.wait_group 0;" ::: "memory");
}
__device__ __forceinline__ void ldsm4(uint32_t* r, uint32_t a) {
    asm volatile("ldmatrix.sync.aligned.m8n8.x4.shared.b16 {%0,%1,%2,%3}, [%4];"
                 : "=r"(r[0]), "=r"(r[1]), "=r"(r[2]), "=r"(r[3]) : "r"(a));
}
__device__ __forceinline__ void mma_fp16(float* c, const uint32_t* a, const uint32_t* b) {
    asm volatile(
        "mma.sync.aligned.m16n8k16.row.col.f32.f16.f16.f32 "
        "{%0,%1,%2,%3},{%4,%5,%6,%7},{%8,%9},{%0,%1,%2,%3};"
        : "+f"(c[0]), "+f"(c[1]), "+f"(c[2]), "+f"(c[3])
        : "r"(a[0]), "r"(a[1]), "r"(a[2]), "r"(a[3]), "r"(b[0]), "r"(b[1]));
}
__device__ __forceinline__ void mma_bf16(float* c, const uint32_t* a, const uint32_t* b) {
    asm volatile(
        "mma.sync.aligned.m16n8k16.row.col.f32.bf16.bf16.f32 "
        "{%0,%1,%2,%3},{%4,%5,%6,%7},{%8,%9},{%0,%1,%2,%3};"
        : "+f"(c[0]), "+f"(c[1]), "+f"(c[2]), "+f"(c[3])
        : "r"(a[0]), "r"(a[1]), "r"(a[2]), "r"(a[3]), "r"(b[0]), "r"(b[1]));
}

// ---------------------------------------------------------------- init ------
__global__ void init_kernel() {
    int i = blockIdx.x * blockDim.x + threadIdx.x;
    if (i < BATCH * HID) {
        g_c[i] = 0.f;
        g_hhi[i] = __float2bfloat16(0.f);
        g_hlo[i] = __float2bfloat16(0.f);
    }
}

// --------------------------------- x_proj -> gate_base[b][perm(r)] ----------
__global__ void xproj_kernel(const float4* __restrict__ feat4,
                             const float4* __restrict__ wih4,
                             const float*  __restrict__ b_ih,
                             const float*  __restrict__ b_hh) {
    __shared__ float4 fs[BATCH * 32];
    int tid = threadIdx.x;
    int rl  = tid & 31;
    int bg  = tid >> 5;
    int r   = blockIdx.x * 32 + rl;
    float acc[8];
#pragma unroll
    for (int j = 0; j < 8; j++) acc[j] = 0.f;
    for (int ec = 0; ec < 4; ec++) {
        __syncthreads();
#pragma unroll
        for (int i = 0; i < 8; i++) {
            int lin = i * 256 + tid;
            int b = lin >> 5, q = lin & 31;
            fs[lin] = feat4[b * 128 + ec * 32 + q];
        }
        __syncthreads();
#pragma unroll 4
        for (int eq = 0; eq < 32; eq++) {
            float4 w = wih4[r * 128 + ec * 32 + eq];
#pragma unroll
            for (int jj = 0; jj < 8; jj++) {
                float4 f = fs[(bg * 8 + jj) * 32 + eq];
                acc[jj] += w.x * f.x + w.y * f.y + w.z * f.z + w.w * f.w;
            }
        }
    }
    float bias = b_ih[r] + b_hh[r];
    int p = perm_row(r);
#pragma unroll
    for (int jj = 0; jj < 8; jj++)
        g_gate_base[(bg * 8 + jj) * G4 + p] = acc[jj] + bias;
}

// ---------------------------------------- W_fc fp32 -> fp16 (hi only) -------
__global__ void convW_kernel(const float4* __restrict__ w) {
    int n = blockIdx.x;
    int q = threadIdx.x;
    float4 v = w[(size_t)n * 256 + q];
    __half h0 = __float2half_rn(v.x), h1 = __float2half_rn(v.y);
    __half h2 = __float2half_rn(v.z), h3 = __float2half_rn(v.w);
    uint32_t a = ((uint32_t)__half_as_ushort(h1) << 16) | __half_as_ushort(h0);
    uint32_t b = ((uint32_t)__half_as_ushort(h3) << 16) | __half_as_ushort(h2);
    ((uint2*)(g_Whi + (size_t)n * KDIM))[q] = make_uint2(a, b);
}

// ----------------------- W_hh fp32 -> bf16 hi/lo, gate-interleaved rows -----
__global__ void convWhh_kernel(const float4* __restrict__ w) {
    int r = blockIdx.x;              // source row 0..4095
    int q = threadIdx.x;             // 0..255
    float4 v = w[(size_t)r * 256 + q];
    float x[4] = {v.x, v.y, v.z, v.w};
    __nv_bfloat16 hi[4], lo[4];
#pragma unroll
    for (int j = 0; j < 4; j++) {
        hi[j] = __float2bfloat16_rn(x[j]);
        lo[j] = __float2bfloat16_rn(x[j] - __bfloat162float(hi[j]));
    }
    uint32_t h01 = ((uint32_t)__bfloat16_as_ushort(hi[1]) << 16) | __bfloat16_as_ushort(hi[0]);
    uint32_t h23 = ((uint32_t)__bfloat16_as_ushort(hi[3]) << 16) | __bfloat16_as_ushort(hi[2]);
    uint32_t l01 = ((uint32_t)__bfloat16_as_ushort(lo[1]) << 16) | __bfloat16_as_ushort(lo[0]);
    uint32_t l23 = ((uint32_t)__bfloat16_as_ushort(lo[3]) << 16) | __bfloat16_as_ushort(lo[2]);
    int p = perm_row(r);
    ((uint2*)(g_whh_hi + (size_t)p * KDIM))[q] = make_uint2(h01, h23);
    ((uint2*)(g_whh_lo + (size_t)p * KDIM))[q] = make_uint2(l01, l23);
}

// --------------------- fused LSTM step: mma (bf16 3-pass) + gates -----------
// 64 CTAs x 128 thr. CTA bx owns permuted rows [bx*64, bx*64+64) = 16 hidden
// units x 4 gates. Full K=1024, BK=64, 2-stage cp.async.
#define RPITCH  144                   // 64k*2B + 16
#define R_HALF  (64 * RPITCH)         // 9216
#define R_AT    (2 * R_HALF)
#define R_BT    (2 * R_HALF)
#define R_STAGE (R_AT + R_BT)         // 36864
#define R_SMEM  (2 * R_STAGE)         // 73728
#define GPITCH  66

__device__ __forceinline__ void rec_load(uint32_t sbase, int stage, int it,
                                         int tid, int n0) {
    int k0 = it * 64;
    uint32_t sA = sbase + (uint32_t)stage * R_STAGE;
    uint32_t sB = sA + R_AT;
#pragma unroll
    for (int r = 0; r < 8; r++) {          // A: 1024 cp16 (hi+lo)
        int f = r * 128 + tid;
        int half = f >> 9, q = f & 511;
        int row = q >> 3, qq = q & 7;
        const __nv_bfloat16* src = half ? g_hlo : g_hhi;
        cp16(sA + (uint32_t)(half * R_HALF + row * RPITCH + qq * 16),
             src + (size_t)row * KDIM + k0 + qq * 8);
    }
#pragma unroll
    for (int r = 0; r < 8; r++) {          // B: 1024 cp16 (hi+lo)
        int f = r * 128 + tid;
        int half = f >> 9, q = f & 511;
        int row = q >> 3, qq = q & 7;
        const __nv_bfloat16* src = half ? g_whh_lo : g_whh_hi;
        cp16(sB + (uint32_t)(half * R_HALF + row * RPITCH + qq * 16),
             src + (size_t)(n0 + row) * KDIM + k0 + qq * 8);
    }
}

__global__ void __launch_bounds__(128)
lstm_step_tc(int t) {
    extern __shared__ char sm[];
    uint32_t sbase = smem_u32(sm);
    int tid = threadIdx.x, lane = tid & 31, wid = tid >> 5;
    int wm = wid & 1, wn = wid >> 1;       // warp: 32m x 32n
    int bx = blockIdx.x;
    int n0 = bx * 64;                      // permuted-row base

    float acc[2][4][4];
#pragma unroll
    for (int i = 0; i < 2; i++)
#pragma unroll
        for (int j = 0; j < 4; j++)
#pragma unroll
            for (int k = 0; k < 4; k++) acc[i][j][k] = 0.f;

    rec_load(sbase, 0, 0, tid, n0);
    cp_commit();

    const int NIT = KDIM / 64;             // 16
    for (int it = 0; it < NIT; it++) {
        if (it + 1 < NIT) {
            rec_load(sbase, (it + 1) & 1, it + 1, tid, n0);
            cp_commit();
            cp_wait1();
        } else {
            cp_wait0();
        }
        __syncthreads();
        uint32_t sA = sbase + (uint32_t)(it & 1) * R_STAGE;
        uint32_t sB = sA + R_AT;
#pragma unroll
        for (int kk = 0; kk < 4; kk++) {
            uint32_t a_hi[2][4], a_lo[2][4];
#pragma unroll
            for (int mt = 0; mt < 2; mt++) {
                uint32_t arow = (uint32_t)((wm * 32 + mt * 16 + (lane & 15)) * RPITCH
                                           + kk * 32 + (lane >> 4) * 16);
                ldsm4(a_hi[mt], sA + arow);
                ldsm4(a_lo[mt], sA + R_HALF + arow);
            }
#pragma unroll
            for (int bq = 0; bq < 2; bq++) {
                uint32_t b_hi[4], b_lo[4];
                int nrow = wn * 32 + bq * 16 + ((lane >> 4) << 3) + (lane & 7);
                uint32_t boff = (uint32_t)(nrow * RPITCH + kk * 32 + ((lane >> 3) & 1) * 16);
                ldsm4(b_hi, sB + boff);
                ldsm4(b_lo, sB + R_HALF + boff);
#pragma unroll
                for (int mt = 0; mt < 2; mt++)
#pragma unroll
                    for (int s = 0; s < 2; s++) {
                        float* c = acc[mt][bq * 2 + s];
                        mma_bf16(c, a_hi[mt], &b_hi[s * 2]);   // hi*hi
                        mma_bf16(c, a_hi[mt], &b_lo[s * 2]);   // hi*lo
                        mma_bf16(c, a_lo[mt], &b_hi[s * 2]);   // lo*hi
                    }
            }
        }
        __syncthreads();
    }

    // ---- dump gates to smem (reuse stage memory) ----
    float* gsm = (float*)sm;               // [64][GPITCH]
#pragma unroll
    for (int mt = 0; mt < 2; mt++) {
        int m = wm * 32 + mt * 16 + (lane >> 2);
#pragma unroll
        for (int nt = 0; nt < 4; nt++) {
            int n = wn * 32 + nt * 8 + (lane & 3) * 2;
            *(float2*)&gsm[m * GPITCH + n] = make_float2(acc[mt][nt][0], acc[mt][nt][1]);
            *(float2*)&gsm[(m + 8) * GPITCH + n] = make_float2(acc[mt][nt][2], acc[mt][nt][3]);
        }
    }
    __syncthreads();

    // ---- fuse: 64 b x 16 j cells ----
#pragma unroll
    for (int i = 0; i < 8; i++) {
        int idx = i * 128 + tid;
        int b = idx >> 4, jl = idx & 15;
        float gate[4];
#pragma unroll
        for (int gi = 0; gi < 4; gi++)
            gate[gi] = gsm[b * GPITCH + gi * 16 + jl]
                     + g_gate_base[(size_t)b * G4 + n0 + gi * 16 + jl];
        float iv = 1.f / (1.f + expf(-gate[0]));
        float fv = 1.f / (1.f + expf(-gate[1]));
        float gv = tanhf(gate[2]);
        float ov = 1.f / (1.f + expf(-gate[3]));
        int j  = bx * 16 + jl;
        int ci = b * HID + j;
        float c = fv * g_c[ci] + iv * gv;
        g_c[ci] = c;
        float h = ov * tanhf(c);
        __nv_bfloat16 hi = __float2bfloat16_rn(h);
        g_hhi[ci] = hi;
        g_hlo[ci] = __float2bfloat16_rn(h - __bfloat162float(hi));
        g_Ah[(size_t)(b * TSTEPS + t) * KDIM + j] = __float2half_rn(h);
    }
}

// --------------------- vocab GEMM: fp16 single-pass, 128x256x32, 3-stage ----
#define BN      256
#define BK      32
#define NITER   (KDIM / BK)          // 32
#define APITCH  80                   // 32k*2B + 16 pad
#define A_T     (128 * APITCH)       // 10240
#define B_T     (256 * APITCH)       // 20480
#define STAGEB  (A_T + B_T)          // 30720
#define NSTAGE  3
#define SMEMB   (NSTAGE * STAGEB)    // 92160

__device__ __forceinline__ void gemm_load(uint32_t sbase, int stage, int it,
                                          int tid, int m0, int n0) {
    int kk0 = it * BK;
    uint32_t sA = sbase + (uint32_t)stage * STAGEB;
    uint32_t sB = sA + A_T;
    {                                       // A: 512 cp16
        int row = tid >> 2, q = tid & 3;
        cp16(sA + (uint32_t)(row * APITCH + q * 16),
             g_Ah + (size_t)(m0 + row) * KDIM + kk0 + q * 8);
    }
#pragma unroll
    for (int r = 0; r < 2; r++) {           // B: 1024 cp16 (hi only)
        int f = r * 512 + tid;
        int row = f >> 2, q = f & 3;
        int n = n0 + row;
        if (n > VOCAB - 1) n = VOCAB - 1;   // clamp: results discarded
        cp16(sB + (uint32_t)(row * APITCH + q * 16),
             g_Whi + (size_t)n * KDIM + kk0 + q * 8);
    }
}

__global__ void __launch_bounds__(512, 1)
vocab_gemm_hmma(const float* __restrict__ b_fc, float* __restrict__ out) {
    extern __shared__ char sm[];
    uint32_t sbase = smem_u32(sm);
    int tid = threadIdx.x, lane = tid & 31, wid = tid >> 5;
    int wm = wid & 3, wn = wid >> 2;           // warp: 32(m) x 64(n)
    int m0 = blockIdx.x * 128;
    int n0 = blockIdx.y * BN;

    float acc[2][8][4];
#pragma unroll
    for (int i = 0; i < 2; i++)
#pragma unroll
        for (int j = 0; j < 8; j++)
#pragma unroll
            for (int k = 0; k < 4; k++) acc[i][j][k] = 0.f;

    gemm_load(sbase, 0, 0, tid, m0, n0); cp_commit();
    gemm_load(sbase, 1, 1, tid, m0, n0); cp_commit();

    for (int it = 0; it < NITER; it++) {
        cp_wait1();
        __syncthreads();
        if (it + 2 < NITER) gemm_load(sbase, (it + 2) % NSTAGE, it + 2, tid, m0, n0);
        cp_commit();

        uint32_t sA = sbase + (uint32_t)(it % NSTAGE) * STAGEB;
        uint32_t sB = sA + A_T;
#pragma unroll
        for (int kk = 0; kk < 2; kk++) {
            uint32_t a[2][4];
#pragma unroll
            for (int mt = 0; mt < 2; mt++)
                ldsm4(a[mt], sA + (uint32_t)((wm * 32 + mt * 16 + (lane & 15)) * APITCH
                                             + kk * 32 + (lane >> 4) * 16));
#pragma unroll
            for (int bq = 0; bq < 4; bq++) {
                uint32_t b_hi[4];
                int nrow = wn * 64 + bq * 16 + ((lane >> 4) << 3) + (lane & 7);
                uint32_t boff = (uint32_t)(nrow * APITCH + kk * 32 + ((lane >> 3) & 1) * 16);
                ldsm4(b_hi, sB + boff);
#pragma unroll
                for (int mt = 0; mt < 2; mt++)
#pragma unroll
                    for (int s = 0; s < 2; s++)
                        mma_fp16(acc[mt][bq * 2 + s], a[mt], &b_hi[s * 2]);
            }
        }
        __syncthreads();
    }

#pragma unroll
    for (int mt = 0; mt < 2; mt++) {
        int r0 = m0 + wm * 32 + mt * 16 + (lane >> 2);
        float* o0 = out + (size_t)r0 * VOCAB;
        float* o1 = out + (size_t)(r0 + 8) * VOCAB;
#pragma unroll
        for (int nt = 0; nt < 8; nt++) {
            int col = n0 + wn * 64 + nt * 8 + (lane & 3) * 2;
            if (col < VOCAB) {
                float bz = b_fc[col];
                o0[col] = acc[mt][nt][0] + bz;
                o1[col] = acc[mt][nt][2] + bz;
            }
            if (col + 1 < VOCAB) {
                float bz = b_fc[col + 1];
                o0[col + 1] = acc[mt][nt][1] + bz;
                o1[col + 1] = acc[mt][nt][3] + bz;
            }
        }
    }
}

// ---------------------------------------------------------------------------
extern "C" void kernel_launch(void* const* d_in, const int* in_sizes, int n_in,
                              void* d_out, int out_size) {
    const float* features = (const float*)d_in[0];
    const float* W_ih     = (const float*)d_in[1];
    const float* W_hh     = (const float*)d_in[2];
    const float* b_ih     = (const float*)d_in[3];
    const float* b_hh     = (const float*)d_in[4];
    const float* W_fc     = (const float*)d_in[5];
    const float* b_fc     = (const float*)d_in[6];
    (void)in_sizes; (void)n_in; (void)out_size;

    cudaFuncSetAttribute(vocab_gemm_hmma,
                         cudaFuncAttributeMaxDynamicSharedMemorySize, SMEMB);
    cudaFuncSetAttribute(lstm_step_tc,
                         cudaFuncAttributeMaxDynamicSharedMemorySize, R_SMEM);

    init_kernel<<<(BATCH * HID + 255) / 256, 256>>>();
    xproj_kernel<<<128, 256>>>((const float4*)features, (const float4*)W_ih,
                               b_ih, b_hh);
    convW_kernel<<<VOCAB, 256>>>((const float4*)W_fc);
    convWhh_kernel<<<G4, 256>>>((const float4*)W_hh);   // last: leaves W_hh L2-warm

    for (int t = 0; t < TSTEPS; t++)
        lstm_step_tc<<<64, 128, R_SMEM>>>(t);

    dim3 grid(MROWS / 128, (VOCAB + BN - 1) / BN);   // (9, 197)
    vocab_gemm_hmma<<<grid, 512, SMEMB>>>(b_fc, (float*)d_out);
}

// round 9
// speedup vs baseline: 5.8336x; 1.2201x over previous
#include <cuda_runtime.h>
#include <cuda_fp16.h>
#include <cuda_bf16.h>
#include <math.h>
#include <stdint.h>

#define BATCH  64
#define EMBED  512
#define HID    1024
#define G4     4096
#define VOCAB  50257
#define TSTEPS 18
#define MROWS  (BATCH*TSTEPS)   // 1152
#define KDIM   1024
#define PCTA   128              // persistent LSTM CTAs (<=148 SMs)

// ---------------- device scratch (static device globals; no allocs) ---------
__device__ float g_gate_base[BATCH * G4];            // [b][p]  (permuted rows)
__device__ float g_c[BATCH * HID];                   // [b][j]
__device__ int   g_bar[TSTEPS];                      // grid-barrier counters
__device__ __nv_bfloat16 g_hhi[BATCH * HID];         // h hi [b][j]
__device__ __nv_bfloat16 g_hlo[BATCH * HID];         // h lo
__device__ __nv_bfloat16 g_whh_hi[G4 * KDIM];        // permuted rows, 8 MB
__device__ __nv_bfloat16 g_whh_lo[G4 * KDIM];        // 8 MB
__device__ __half g_Ah[MROWS * KDIM];                // vocab A fp16  2.3 MB
__device__ __half g_Whi[(size_t)VOCAB * KDIM];       // 103 MB

// permuted row: r = gi*HID + j  ->  p = (j>>3)*32 + gi*8 + (j&7)
__device__ __forceinline__ int perm_row(int r) {
    int gi = r >> 10, j = r & (HID - 1);
    return ((j >> 3) << 5) + (gi << 3) + (j & 7);
}

// ---------------------------------------------------------------- helpers ---
__device__ __forceinline__ uint32_t smem_u32(const void* p) {
    uint32_t a;
    asm("{ .reg .u64 t; cvta.to.shared.u64 t, %1; cvt.u32.u64 %0, t; }"
        : "=r"(a) : "l"(p));
    return a;
}
__device__ __forceinline__ void cp16(uint32_t s, const void* g) {
    asm volatile("cp.async.cg.shared.global [%0], [%1], 16;" :: "r"(s), "l"(g) : "memory");
}
__device__ __forceinline__ void cp_commit() {
    asm volatile("cp.async.commit_group;" ::: "memory");
}
__device__ __forceinline__ void cp_wait1() {
    asm volatile("cp.async.wait_group 1;" ::: "memory");
}
__device__ __forceinline__ void cp_wait0() {
    asm volatile("cp.async.wait_group 0;" ::: "memory");
}
__device__ __forceinline__ void ldsm4(uint32_t* r, uint32_t a) {
    asm volatile("ldmatrix.sync.aligned.m8n8.x4.shared.b16 {%0,%1,%2,%3}, [%4];"
                 : "=r"(r[0]), "=r"(r[1]), "=r"(r[2]), "=r"(r[3]) : "r"(a));
}
__device__ __forceinline__ void mma_fp16(float* c, const uint32_t* a, const uint32_t* b) {
    asm volatile(
        "mma.sync.aligned.m16n8k16.row.col.f32.f16.f16.f32 "
        "{%0,%1,%2,%3},{%4,%5,%6,%7},{%8,%9},{%0,%1,%2,%3};"
        : "+f"(c[0]), "+f"(c[1]), "+f"(c[2]), "+f"(c[3])
        : "r"(a[0]), "r"(a[1]), "r"(a[2]), "r"(a[3]), "r"(b[0]), "r"(b[1]));
}
__device__ __forceinline__ void mma_bf16(float* c, const uint32_t* a, const uint32_t* b) {
    asm volatile(
        "mma.sync.aligned.m16n8k16.row.col.f32.bf16.bf16.f32 "
        "{%0,%1,%2,%3},{%4,%5,%6,%7},{%8,%9},{%0,%1,%2,%3};"
        : "+f"(c[0]), "+f"(c[1]), "+f"(c[2]), "+f"(c[3])
        : "r"(a[0]), "r"(a[1]), "r"(a[2]), "r"(a[3]), "r"(b[0]), "r"(b[1]));
}

// ---------------------------------------------------------------- init ------
__global__ void init_kernel() {
    int i = blockIdx.x * blockDim.x + threadIdx.x;
    if (i < BATCH * HID) {
        g_c[i] = 0.f;
        g_hhi[i] = __float2bfloat16(0.f);
        g_hlo[i] = __float2bfloat16(0.f);
    }
    if (i < TSTEPS) g_bar[i] = 0;
}

// --------------------------------- x_proj -> gate_base[b][perm(r)] ----------
__global__ void xproj_kernel(const float4* __restrict__ feat4,
                             const float4* __restrict__ wih4,
                             const float*  __restrict__ b_ih,
                             const float*  __restrict__ b_hh) {
    __shared__ float4 fs[BATCH * 32];
    int tid = threadIdx.x;
    int rl  = tid & 31;
    int bg  = tid >> 5;
    int r   = blockIdx.x * 32 + rl;
    float acc[8];
#pragma unroll
    for (int j = 0; j < 8; j++) acc[j] = 0.f;
    for (int ec = 0; ec < 4; ec++) {
        __syncthreads();
#pragma unroll
        for (int i = 0; i < 8; i++) {
            int lin = i * 256 + tid;
            int b = lin >> 5, q = lin & 31;
            fs[lin] = feat4[b * 128 + ec * 32 + q];
        }
        __syncthreads();
#pragma unroll 4
        for (int eq = 0; eq < 32; eq++) {
            float4 w = wih4[r * 128 + ec * 32 + eq];
#pragma unroll
            for (int jj = 0; jj < 8; jj++) {
                float4 f = fs[(bg * 8 + jj) * 32 + eq];
                acc[jj] += w.x * f.x + w.y * f.y + w.z * f.z + w.w * f.w;
            }
        }
    }
    float bias = b_ih[r] + b_hh[r];
    int p = perm_row(r);
#pragma unroll
    for (int jj = 0; jj < 8; jj++)
        g_gate_base[(bg * 8 + jj) * G4 + p] = acc[jj] + bias;
}

// --------------------------- W_fc fp32 -> fp16, MLP=4 -----------------------
__global__ void convW_kernel(const float4* __restrict__ w) {
    const size_t total = (size_t)VOCAB * 256;     // float4 count
    size_t base = ((size_t)blockIdx.x * 256 + threadIdx.x) * 4;
    float4 v[4];
    bool ok[4];
#pragma unroll
    for (int i = 0; i < 4; i++) {
        ok[i] = (base + i) < total;
        if (ok[i]) v[i] = w[base + i];
    }
    uint2* dst = (uint2*)g_Whi;
#pragma unroll
    for (int i = 0; i < 4; i++) {
        if (!ok[i]) continue;
        __half h0 = __float2half_rn(v[i].x), h1 = __float2half_rn(v[i].y);
        __half h2 = __float2half_rn(v[i].z), h3 = __float2half_rn(v[i].w);
        uint32_t a = ((uint32_t)__half_as_ushort(h1) << 16) | __half_as_ushort(h0);
        uint32_t b = ((uint32_t)__half_as_ushort(h3) << 16) | __half_as_ushort(h2);
        dst[base + i] = make_uint2(a, b);
    }
}

// ----------------------- W_hh fp32 -> bf16 hi/lo, permuted rows -------------
__global__ void convWhh_kernel(const float4* __restrict__ w) {
    int r = blockIdx.x;              // source row 0..4095
    int q = threadIdx.x;             // 0..255
    float4 v = w[(size_t)r * 256 + q];
    float x[4] = {v.x, v.y, v.z, v.w};
    __nv_bfloat16 hi[4], lo[4];
#pragma unroll
    for (int j = 0; j < 4; j++) {
        hi[j] = __float2bfloat16_rn(x[j]);
        lo[j] = __float2bfloat16_rn(x[j] - __bfloat162float(hi[j]));
    }
    uint32_t h01 = ((uint32_t)__bfloat16_as_ushort(hi[1]) << 16) | __bfloat16_as_ushort(hi[0]);
    uint32_t h23 = ((uint32_t)__bfloat16_as_ushort(hi[3]) << 16) | __bfloat16_as_ushort(hi[2]);
    uint32_t l01 = ((uint32_t)__bfloat16_as_ushort(lo[1]) << 16) | __bfloat16_as_ushort(lo[0]);
    uint32_t l23 = ((uint32_t)__bfloat16_as_ushort(lo[3]) << 16) | __bfloat16_as_ushort(lo[2]);
    int p = perm_row(r);
    ((uint2*)(g_whh_hi + (size_t)p * KDIM))[q] = make_uint2(h01, h23);
    ((uint2*)(g_whh_lo + (size_t)p * KDIM))[q] = make_uint2(l01, l23);
}

// -------------------- persistent LSTM: 18 steps, 1 launch -------------------
// 128 CTAs x 128 thr. CTA bx owns permuted rows [bx*32, bx*32+32) = 8 hidden
// units x 4 gates. W_hh slice (hi+lo) resident in smem; A streams per step.
#define BPITCH  2064                  // 1024k*2B + 16
#define B_RES   (32 * BPITCH)         // 66048 per half
#define AOFF    (2 * B_RES)           // 132096
#define APITCH2 144                   // 64k*2B + 16
#define A_HALF  (64 * APITCH2)        // 9216
#define A_STG   (2 * A_HALF)          // hi+lo 18432
#define P_SMEM  (AOFF + 2 * A_STG)    // 168960
#define GPITCH  34                    // EVEN: float2 stores stay 8B-aligned

__device__ __forceinline__ void loadA_step(uint32_t sbase, int stage, int it,
                                           int tid) {
    int k0 = it * 64;
    uint32_t sA = sbase + AOFF + (uint32_t)stage * A_STG;
#pragma unroll
    for (int r = 0; r < 8; r++) {          // 1024 cp16 (hi+lo)
        int f = r * 128 + tid;
        int half = f >> 9, q = f & 511;
        int row = q >> 3, qq = q & 7;
        const __nv_bfloat16* src = half ? g_hlo : g_hhi;
        cp16(sA + (uint32_t)(half * A_HALF + row * APITCH2 + qq * 16),
             src + (size_t)row * KDIM + k0 + qq * 8);
    }
}

__global__ void __launch_bounds__(128)
lstm_persist() {
    extern __shared__ char sm[];
    uint32_t sbase = smem_u32(sm);
    int tid = threadIdx.x, lane = tid & 31, wid = tid >> 5;
    int wm = wid & 1, wn = wid >> 1;       // warp: 32m x 16n
    int bx = blockIdx.x;
    int n0 = bx * 32;                      // permuted-row base

    // ---- load resident W slice: 32 rows x 1024 k, hi+lo ----
#pragma unroll 4
    for (int r = 0; r < 32; r++) {         // hi: 4096 cp16
        int f = r * 128 + tid;
        int row = f >> 7, u = f & 127;
        cp16(sbase + (uint32_t)(row * BPITCH + u * 16),
             g_whh_hi + (size_t)(n0 + row) * KDIM + u * 8);
    }
#pragma unroll 4
    for (int r = 0; r < 32; r++) {         // lo
        int f = r * 128 + tid;
        int row = f >> 7, u = f & 127;
        cp16(sbase + (uint32_t)(B_RES + row * BPITCH + u * 16),
             g_whh_lo + (size_t)(n0 + row) * KDIM + u * 8);
    }
    cp_commit();
    cp_wait0();
    __syncthreads();

    float* gsm = (float*)(sm + AOFF);      // gate dump (reuses A-stage smem)

    for (int t = 0; t < TSTEPS; t++) {
        float acc[2][2][4];
#pragma unroll
        for (int i = 0; i < 2; i++)
#pragma unroll
            for (int j = 0; j < 2; j++)
#pragma unroll
                for (int k = 0; k < 4; k++) acc[i][j][k] = 0.f;

        loadA_step(sbase, 0, 0, tid);
        cp_commit();

        const int NIT = KDIM / 64;         // 16
        for (int it = 0; it < NIT; it++) {
            if (it + 1 < NIT) {
                loadA_step(sbase, (it + 1) & 1, it + 1, tid);
                cp_commit();
                cp_wait1();
            } else {
                cp_wait0();
            }
            __syncthreads();
            uint32_t sA = sbase + AOFF + (uint32_t)(it & 1) * A_STG;
#pragma unroll
            for (int kk = 0; kk < 4; kk++) {
                uint32_t a_hi[2][4], a_lo[2][4];
#pragma unroll
                for (int mt = 0; mt < 2; mt++) {
                    uint32_t arow = (uint32_t)((wm * 32 + mt * 16 + (lane & 15)) * APITCH2
                                               + kk * 32 + (lane >> 4) * 16);
                    ldsm4(a_hi[mt], sA + arow);
                    ldsm4(a_lo[mt], sA + A_HALF + arow);
                }
                uint32_t b_hi[4], b_lo[4];
                {
                    int nrow = wn * 16 + ((lane >> 4) << 3) + (lane & 7);
                    uint32_t boff = (uint32_t)(nrow * BPITCH + it * 128 + kk * 32
                                               + ((lane >> 3) & 1) * 16);
                    ldsm4(b_hi, sbase + boff);
                    ldsm4(b_lo, sbase + B_RES + boff);
                }
#pragma unroll
                for (int mt = 0; mt < 2; mt++)
#pragma unroll
                    for (int s = 0; s < 2; s++) {
                        float* c = acc[mt][s];
                        mma_bf16(c, a_hi[mt], &b_hi[s * 2]);   // hi*hi
                        mma_bf16(c, a_hi[mt], &b_lo[s * 2]);   // hi*lo
                        mma_bf16(c, a_lo[mt], &b_hi[s * 2]);   // lo*hi
                    }
            }
            __syncthreads();
        }

        // ---- dump gates to smem ----
#pragma unroll
        for (int mt = 0; mt < 2; mt++) {
            int m = wm * 32 + mt * 16 + (lane >> 2);
#pragma unroll
            for (int s = 0; s < 2; s++) {
                int n = wn * 16 + s * 8 + (lane & 3) * 2;
                *(float2*)&gsm[m * GPITCH + n] = make_float2(acc[mt][s][0], acc[mt][s][1]);
                *(float2*)&gsm[(m + 8) * GPITCH + n] = make_float2(acc[mt][s][2], acc[mt][s][3]);
            }
        }
        __syncthreads();

        // ---- fuse: 64 b x 8 j cells ----
#pragma unroll
        for (int i = 0; i < 4; i++) {
            int idx = i * 128 + tid;
            int b = idx >> 3, jl = idx & 7;
            float gate[4];
#pragma unroll
            for (int gi = 0; gi < 4; gi++)
                gate[gi] = gsm[b * GPITCH + gi * 8 + jl]
                         + g_gate_base[(size_t)b * G4 + n0 + gi * 8 + jl];
            float iv = 1.f / (1.f + expf(-gate[0]));
            float fv = 1.f / (1.f + expf(-gate[1]));
            float gv = tanhf(gate[2]);
            float ov = 1.f / (1.f + expf(-gate[3]));
            int j  = bx * 8 + jl;
            int ci = b * HID + j;
            float c = fv * g_c[ci] + iv * gv;
            g_c[ci] = c;
            float h = ov * tanhf(c);
            __nv_bfloat16 hb = __float2bfloat16_rn(h);
            g_hhi[ci] = hb;
            g_hlo[ci] = __float2bfloat16_rn(h - __bfloat162float(hb));
            g_Ah[(size_t)(b * TSTEPS + t) * KDIM + j] = __float2half_rn(h);
        }

        // ---- grid barrier (skip after final step) ----
        if (t + 1 < TSTEPS) {
            __threadfence();
            __syncthreads();
            if (tid == 0) {
                atomicAdd(&g_bar[t], 1);
                while (atomicAdd(&g_bar[t], 0) < PCTA) { }
                __threadfence();
            }
            __syncthreads();
        }
    }
}

// --------------------- vocab GEMM: fp16 single-pass, 128x256x64, 2-stage ----
#define BN      256
#define BK      64
#define NITER   (KDIM / BK)          // 16
#define APITCH  144                  // 64k*2B + 16
#define A_T     (128 * APITCH)       // 18432
#define B_T     (256 * APITCH)       // 36864
#define STAGEB  (A_T + B_T)          // 55296
#define SMEMB   (2 * STAGEB)         // 110592

__device__ __forceinline__ void gemm_load(uint32_t sbase, int stage, int it,
                                          int tid, int m0, int n0) {
    int kk0 = it * BK;
    uint32_t sA = sbase + (uint32_t)stage * STAGEB;
    uint32_t sB = sA + A_T;
#pragma unroll
    for (int r = 0; r < 2; r++) {           // A: 1024 cp16
        int f = r * 512 + tid;
        int row = f >> 3, q = f & 7;
        cp16(sA + (uint32_t)(row * APITCH + q * 16),
             g_Ah + (size_t)(m0 + row) * KDIM + kk0 + q * 8);
    }
#pragma unroll
    for (int r = 0; r < 4; r++) {           // B: 2048 cp16
        int f = r * 512 + tid;
        int row = f >> 3, q = f & 7;
        int n = n0 + row;
        if (n > VOCAB - 1) n = VOCAB - 1;   // clamp: results discarded
        cp16(sB + (uint32_t)(row * APITCH + q * 16),
             g_Whi + (size_t)n * KDIM + kk0 + q * 8);
    }
}

__global__ void __launch_bounds__(512, 1)
vocab_gemm_hmma(const float* __restrict__ b_fc, float* __restrict__ out) {
    extern __shared__ char sm[];
    uint32_t sbase = smem_u32(sm);
    int tid = threadIdx.x, lane = tid & 31, wid = tid >> 5;
    int wm = wid & 3, wn = wid >> 2;           // warp: 32(m) x 64(n)
    int m0 = blockIdx.x * 128;
    int n0 = blockIdx.y * BN;

    float acc[2][8][4];
#pragma unroll
    for (int i = 0; i < 2; i++)
#pragma unroll
        for (int j = 0; j < 8; j++)
#pragma unroll
            for (int k = 0; k < 4; k++) acc[i][j][k] = 0.f;

    gemm_load(sbase, 0, 0, tid, m0, n0);
    cp_commit();

    for (int it = 0; it < NITER; it++) {
        if (it + 1 < NITER) {
            gemm_load(sbase, (it + 1) & 1, it + 1, tid, m0, n0);
            cp_commit();
            cp_wait1();
        } else {
            cp_wait0();
        }
        __syncthreads();

        uint32_t sA = sbase + (uint32_t)(it & 1) * STAGEB;
        uint32_t sB = sA + A_T;
#pragma unroll
        for (int kk = 0; kk < 4; kk++) {
            uint32_t a[2][4];
#pragma unroll
            for (int mt = 0; mt < 2; mt++)
                ldsm4(a[mt], sA + (uint32_t)((wm * 32 + mt * 16 + (lane & 15)) * APITCH
                                             + kk * 32 + (lane >> 4) * 16));
#pragma unroll
            for (int bq = 0; bq < 4; bq++) {
                uint32_t b_hi[4];
                int nrow = wn * 64 + bq * 16 + ((lane >> 4) << 3) + (lane & 7);
                uint32_t boff = (uint32_t)(nrow * APITCH + kk * 32 + ((lane >> 3) & 1) * 16);
                ldsm4(b_hi, sB + boff);
#pragma unroll
                for (int mt = 0; mt < 2; mt++)
#pragma unroll
                    for (int s = 0; s < 2; s++)
                        mma_fp16(acc[mt][bq * 2 + s], a[mt], &b_hi[s * 2]);
            }
        }
        __syncthreads();
    }

#pragma unroll
    for (int mt = 0; mt < 2; mt++) {
        int r0 = m0 + wm * 32 + mt * 16 + (lane >> 2);
        float* o0 = out + (size_t)r0 * VOCAB;
        float* o1 = out + (size_t)(r0 + 8) * VOCAB;
#pragma unroll
        for (int nt = 0; nt < 8; nt++) {
            int col = n0 + wn * 64 + nt * 8 + (lane & 3) * 2;
            if (col < VOCAB) {
                float bz = b_fc[col];
                o0[col] = acc[mt][nt][0] + bz;
                o1[col] = acc[mt][nt][2] + bz;
            }
            if (col + 1 < VOCAB) {
                float bz = b_fc[col + 1];
                o0[col + 1] = acc[mt][nt][1] + bz;
                o1[col + 1] = acc[mt][nt][3] + bz;
            }
        }
    }
}

// ---------------------------------------------------------------------------
extern "C" void kernel_launch(void* const* d_in, const int* in_sizes, int n_in,
                              void* d_out, int out_size) {
    const float* features = (const float*)d_in[0];
    const float* W_ih     = (const float*)d_in[1];
    const float* W_hh     = (const float*)d_in[2];
    const float* b_ih     = (const float*)d_in[3];
    const float* b_hh     = (const float*)d_in[4];
    const float* W_fc     = (const float*)d_in[5];
    const float* b_fc     = (const float*)d_in[6];
    (void)in_sizes; (void)n_in; (void)out_size;

    cudaFuncSetAttribute(vocab_gemm_hmma,
                         cudaFuncAttributeMaxDynamicSharedMemorySize, SMEMB);
    cudaFuncSetAttribute(lstm_persist,
                         cudaFuncAttributeMaxDynamicSharedMemorySize, P_SMEM);

    init_kernel<<<(BATCH * HID + 255) / 256, 256>>>();
    xproj_kernel<<<128, 256>>>((const float4*)features, (const float4*)W_ih,
                               b_ih, b_hh);
    convW_kernel<<<(VOCAB + 3) / 4, 256>>>((const float4*)W_fc);
    convWhh_kernel<<<G4, 256>>>((const float4*)W_hh);   // last: W_hh L2-warm

    lstm_persist<<<PCTA, 128, P_SMEM>>>();

    dim3 grid(MROWS / 128, (VOCAB + BN - 1) / BN);   // (9, 197)
    vocab_gemm_hmma<<<grid, 512, SMEMB>>>(b_fc, (float*)d_out);
}